// round 1
// baseline (speedup 1.0000x reference)
#include <cuda_runtime.h>
#include <math.h>

#define NN 50000
#define NE 400000

// ---------------- scratch (device globals; no runtime allocation) ----------------
__device__ __align__(16) float g_q [NN * 128];
__device__ __align__(16) float g_k [NN * 128];
__device__ __align__(16) float g_t1[NN * 128];
__device__ __align__(16) float g_v [NN * 128];
__device__ __align__(16) float g_P [(size_t)NN * 1024];   // [N][8][128] = v_hslice @ wc_hslice
__device__ __align__(16) float g_a [(size_t)NE * 8];      // logits -> exp values
__device__ unsigned       g_amax[NN * 8];                  // monotone-encoded float max keys
__device__ float          g_asum[NN * 8];
__device__ float          g_deg [NN];

__device__ __forceinline__ float silu_f(float x) { return x / (1.0f + __expf(-x)); }

// monotone unsigned encoding of float for atomicMax (total order, works for negatives)
__device__ __forceinline__ unsigned fenc(float f) {
    unsigned u = __float_as_uint(f);
    return (u & 0x80000000u) ? ~u : (u | 0x80000000u);
}
__device__ __forceinline__ float fdec(unsigned k) {
    unsigned u = (k & 0x80000000u) ? (k ^ 0x80000000u) : ~k;
    return __uint_as_float(u);
}

// ---------------- C[nrows,128] = act(A[nrows,128] @ W[128,128] + bias) ----------------
// 64 rows x 128 cols per block, 256 threads, thread = 8x4 microtile. W + A tile in smem.
__global__ void __launch_bounds__(256) node_gemm128(
    const float* __restrict__ A, const float* __restrict__ W,
    const float* __restrict__ bias, float* __restrict__ C,
    int nrows, int act)
{
    extern __shared__ float sm[];
    float* Ws = sm;          // 128*128
    float* As = sm + 16384;  // 64*128
    int tid = threadIdx.x;

    float4* Ws4 = (float4*)Ws;
    const float4* W4 = (const float4*)W;
#pragma unroll
    for (int i = 0; i < 16; i++) Ws4[tid + 256 * i] = W4[tid + 256 * i];

    int row0 = blockIdx.x * 64;
    float4* As4 = (float4*)As;
#pragma unroll
    for (int i = 0; i < 8; i++) {
        int idx = tid + 256 * i;     // 2048 float4 = 64 rows * 32 f4
        int r = idx >> 5, c = idx & 31;
        float4 val = make_float4(0.f, 0.f, 0.f, 0.f);
        if (row0 + r < nrows) val = *(const float4*)(A + (size_t)(row0 + r) * 128 + c * 4);
        As4[idx] = val;
    }
    __syncthreads();

    int tx = tid & 31, ty = tid >> 5;
    int c0 = tx * 4, r0 = ty * 8;
    float acc[8][4];
#pragma unroll
    for (int i = 0; i < 8; i++) { acc[i][0] = acc[i][1] = acc[i][2] = acc[i][3] = 0.f; }

#pragma unroll 4
    for (int kk = 0; kk < 128; kk++) {
        float4 w = Ws4[kk * 32 + tx];
#pragma unroll
        for (int i = 0; i < 8; i++) {
            float a = As[(r0 + i) * 128 + kk];
            acc[i][0] = fmaf(a, w.x, acc[i][0]);
            acc[i][1] = fmaf(a, w.y, acc[i][1]);
            acc[i][2] = fmaf(a, w.z, acc[i][2]);
            acc[i][3] = fmaf(a, w.w, acc[i][3]);
        }
    }

    float4 b4 = *(const float4*)(bias + c0);
#pragma unroll
    for (int i = 0; i < 8; i++) {
        int row = row0 + r0 + i;
        if (row < nrows) {
            float4 o;
            o.x = acc[i][0] + b4.x; o.y = acc[i][1] + b4.y;
            o.z = acc[i][2] + b4.z; o.w = acc[i][3] + b4.w;
            if (act) { o.x = silu_f(o.x); o.y = silu_f(o.y); o.z = silu_f(o.z); o.w = silu_f(o.w); }
            *(float4*)(C + (size_t)row * 128 + c0) = o;
        }
    }
}

// ---------------- P[j,h,:] = v[j, h*16:(h+1)*16] @ wc[h*16:(h+1)*16, :]  (h = blockIdx.y) ----------------
__global__ void __launch_bounds__(256) p_gemm(
    const float* __restrict__ V, const float* __restrict__ WC,
    float* __restrict__ P, int nrows)
{
    __shared__ float Ws[16 * 128];
    __shared__ float As[64 * 16];
    int tid = threadIdx.x;
    int hh = blockIdx.y;

    float4* Ws4 = (float4*)Ws;
#pragma unroll
    for (int i = 0; i < 2; i++) {
        int idx = tid + 256 * i;  // 512 f4 = 2048 floats
        Ws4[idx] = *(const float4*)(WC + (size_t)hh * 16 * 128 + idx * 4);
    }
    int row0 = blockIdx.x * 64;
    float4* As4 = (float4*)As;
    {
        int idx = tid;            // 256 f4 = 64 rows * 4 f4
        int r = idx >> 2, c = idx & 3;
        float4 val = make_float4(0.f, 0.f, 0.f, 0.f);
        if (row0 + r < nrows) val = *(const float4*)(V + (size_t)(row0 + r) * 128 + hh * 16 + c * 4);
        As4[idx] = val;
    }
    __syncthreads();

    int tx = tid & 31, ty = tid >> 5;
    int c0 = tx * 4, r0 = ty * 8;
    float acc[8][4] = {};
#pragma unroll
    for (int kk = 0; kk < 16; kk++) {
        float4 w = Ws4[kk * 32 + tx];
#pragma unroll
        for (int i = 0; i < 8; i++) {
            float a = As[(r0 + i) * 16 + kk];
            acc[i][0] = fmaf(a, w.x, acc[i][0]);
            acc[i][1] = fmaf(a, w.y, acc[i][1]);
            acc[i][2] = fmaf(a, w.z, acc[i][2]);
            acc[i][3] = fmaf(a, w.w, acc[i][3]);
        }
    }
#pragma unroll
    for (int i = 0; i < 8; i++) {
        int row = row0 + r0 + i;
        if (row < nrows)
            *(float4*)(P + (size_t)row * 1024 + hh * 128 + c0) =
                make_float4(acc[i][0], acc[i][1], acc[i][2], acc[i][3]);
    }
}

// ---------------- reset softmax accumulators ----------------
__global__ void init_kernel() {
    int i = blockIdx.x * blockDim.x + threadIdx.x;
    if (i < NN * 8) { g_amax[i] = 0u; g_asum[i] = 0.f; }
    if (i < NN) g_deg[i] = 0.f;
}

// ---------------- per-edge: re = silu(t@wre+bre); a = sum(q_i*k_j*re) per head; max/deg ----------------
// block = 32 edges. Phase A: block-tiled GEMM (K=64) -> Rs. Phase B: warp per 4 edges, gathers + reduce.
__global__ void __launch_bounds__(256) edge_logits(
    const float* __restrict__ T, const int* __restrict__ EI,
    const float* __restrict__ WRE, const float* __restrict__ BRE)
{
    extern __shared__ float sm[];
    float* Ws = sm;                         // 64*128 = 8192
    float* Ts = sm + 8192;                  // 32*64  = 2048
    float* Rs = sm + 8192 + 2048;           // 32*128 = 4096
    float* Bs = sm + 8192 + 2048 + 4096;    // 128
    int tid = threadIdx.x;

    float4* Ws4 = (float4*)Ws;
#pragma unroll
    for (int i = 0; i < 8; i++) Ws4[tid + 256 * i] = ((const float4*)WRE)[tid + 256 * i];
    if (tid < 128) Bs[tid] = BRE[tid];

    int e0 = blockIdx.x * 32;
    float4* Ts4 = (float4*)Ts;
#pragma unroll
    for (int i = 0; i < 2; i++) {
        int idx = tid + 256 * i;  // 512 f4
        Ts4[idx] = *(const float4*)(T + (size_t)e0 * 64 + idx * 4);
    }
    __syncthreads();

    int tx = tid & 31, ty = tid >> 5;
    int c0 = tx * 4, r0 = ty * 4;
    float acc[4][4] = {};
#pragma unroll 4
    for (int kk = 0; kk < 64; kk++) {
        float4 w = Ws4[kk * 32 + tx];
#pragma unroll
        for (int i = 0; i < 4; i++) {
            float a = Ts[(r0 + i) * 64 + kk];
            acc[i][0] = fmaf(a, w.x, acc[i][0]);
            acc[i][1] = fmaf(a, w.y, acc[i][1]);
            acc[i][2] = fmaf(a, w.z, acc[i][2]);
            acc[i][3] = fmaf(a, w.w, acc[i][3]);
        }
    }
    float4 b4 = *(const float4*)(Bs + c0);
#pragma unroll
    for (int i = 0; i < 4; i++) {
        float4 o;
        o.x = silu_f(acc[i][0] + b4.x); o.y = silu_f(acc[i][1] + b4.y);
        o.z = silu_f(acc[i][2] + b4.z); o.w = silu_f(acc[i][3] + b4.w);
        *(float4*)(Rs + (r0 + i) * 128 + c0) = o;
    }
    __syncthreads();

    int lane = tx;  // warp id == ty
#pragma unroll
    for (int i = 0; i < 4; i++) {
        int el = ty * 4 + i;
        int e = e0 + el;
        int nj = EI[e];
        int ni = EI[NE + e];
        float4 q4 = *(const float4*)(g_q + (size_t)ni * 128 + lane * 4);
        float4 k4 = *(const float4*)(g_k + (size_t)nj * 128 + lane * 4);
        float4 r4 = *(const float4*)(Rs + el * 128 + lane * 4);
        float p = q4.x * k4.x * r4.x + q4.y * k4.y * r4.y
                + q4.z * k4.z * r4.z + q4.w * k4.w * r4.w;
        // 16 channels per head = 4 lanes -> reduce within quad
        p += __shfl_xor_sync(0xffffffffu, p, 1);
        p += __shfl_xor_sync(0xffffffffu, p, 2);
        if ((lane & 3) == 0) {
            int hh = lane >> 2;
            g_a[(size_t)e * 8 + hh] = p;
            atomicMax(&g_amax[ni * 8 + hh], fenc(p));
        }
        if (lane == 0) atomicAdd(&g_deg[ni], 1.0f);
    }
}

// ---------------- a_exp = exp(a - amax[ni]); asum += a_exp ----------------
__global__ void edge_exp(const int* __restrict__ EI) {
    int e = blockIdx.x * blockDim.x + threadIdx.x;
    if (e >= NE) return;
    int ni = EI[NE + e];
#pragma unroll
    for (int hh = 0; hh < 8; hh++) {
        float m = fdec(g_amax[ni * 8 + hh]);
        float ex = __expf(g_a[(size_t)e * 8 + hh] - m);
        g_a[(size_t)e * 8 + hh] = ex;
        atomicAdd(&g_asum[ni * 8 + hh], ex);
    }
}

// ---------------- out[e,:] = bc + sum_h w_h * P[nj,h,:],  w_h = a/asum * sqrt(deg)/4 ----------------
__global__ void __launch_bounds__(256) edge_out(
    const int* __restrict__ EI, const float* __restrict__ BC, float* __restrict__ OUT)
{
    int warp = (blockIdx.x * blockDim.x + threadIdx.x) >> 5;
    int lane = threadIdx.x & 31;
    if (warp >= NE) return;
    int e = warp;
    int nj = EI[e];
    int ni = EI[NE + e];

    float w = 0.f;
    if (lane < 8) {
        float s = g_asum[ni * 8 + lane];
        float d = g_deg[ni];
        w = g_a[(size_t)e * 8 + lane] * (sqrtf(d) * 0.25f) / s;
    }

    int c0 = lane * 4;
    float4 acc = *(const float4*)(BC + c0);
    const float* Pn = g_P + (size_t)nj * 1024;
#pragma unroll
    for (int hh = 0; hh < 8; hh++) {
        float wh = __shfl_sync(0xffffffffu, w, hh);
        float4 p4 = *(const float4*)(Pn + hh * 128 + c0);
        acc.x = fmaf(wh, p4.x, acc.x);
        acc.y = fmaf(wh, p4.y, acc.y);
        acc.z = fmaf(wh, p4.z, acc.z);
        acc.w = fmaf(wh, p4.w, acc.w);
    }
    *(float4*)(OUT + (size_t)e * 128 + c0) = acc;
}

// ---------------- launch ----------------
extern "C" void kernel_launch(void* const* d_in, const int* in_sizes, int n_in,
                              void* d_out, int out_size)
{
    const float* h   = (const float*)d_in[0];
    const float* t   = (const float*)d_in[1];
    const int*   ei  = (const int*)  d_in[2];
    const float* wq  = (const float*)d_in[3];
    const float* bq  = (const float*)d_in[4];
    const float* wk  = (const float*)d_in[5];
    const float* bk  = (const float*)d_in[6];
    const float* wre = (const float*)d_in[7];
    const float* bre = (const float*)d_in[8];
    const float* mw1 = (const float*)d_in[9];
    const float* mb1 = (const float*)d_in[10];
    const float* mw2 = (const float*)d_in[11];
    const float* mb2 = (const float*)d_in[12];
    const float* wc  = (const float*)d_in[13];
    const float* bc  = (const float*)d_in[14];
    float* out = (float*)d_out;

    (void)in_sizes; (void)n_in; (void)out_size;

    // host-side attribute sets / symbol queries: not stream ops, capture-safe
    cudaFuncSetAttribute(node_gemm128, cudaFuncAttributeMaxDynamicSharedMemorySize, 98304);
    cudaFuncSetAttribute(edge_logits,  cudaFuncAttributeMaxDynamicSharedMemorySize, 57856);

    float *q_p, *k_p, *t1_p, *v_p, *P_p;
    cudaGetSymbolAddress((void**)&q_p,  g_q);
    cudaGetSymbolAddress((void**)&k_p,  g_k);
    cudaGetSymbolAddress((void**)&t1_p, g_t1);
    cudaGetSymbolAddress((void**)&v_p,  g_v);
    cudaGetSymbolAddress((void**)&P_p,  g_P);

    int nblk = (NN + 63) / 64;  // 782
    node_gemm128<<<nblk, 256, 98304>>>(h,    wq,  bq,  q_p,  NN, 0);
    node_gemm128<<<nblk, 256, 98304>>>(h,    wk,  bk,  k_p,  NN, 0);
    node_gemm128<<<nblk, 256, 98304>>>(h,    mw1, mb1, t1_p, NN, 1);  // silu
    node_gemm128<<<nblk, 256, 98304>>>(t1_p, mw2, mb2, v_p,  NN, 0);

    dim3 pg(nblk, 8);
    p_gemm<<<pg, 256>>>(v_p, wc, P_p, NN);

    init_kernel<<<(NN * 8 + 255) / 256, 256>>>();

    edge_logits<<<NE / 32, 256, 57856>>>(t, ei, wre, bre);
    edge_exp<<<(NE + 255) / 256, 256>>>(ei);
    edge_out<<<NE / 8, 256>>>(ei, bc, out);
}

// round 2
// speedup vs baseline: 1.0022x; 1.0022x over previous
#include <cuda_runtime.h>
#include <math.h>

#define NN 50000
#define NE 400000

// ---------------- scratch (device globals; no runtime allocation) ----------------
__device__ __align__(16) float g_q [NN * 128];
__device__ __align__(16) float g_k [NN * 128];
__device__ __align__(16) float g_t1[NN * 128];
__device__ __align__(16) float g_v [NN * 128];
__device__ __align__(16) float g_P [(size_t)NN * 1024];   // [N][8][128] = v_hslice @ wc_hslice
__device__ __align__(16) float g_a [(size_t)NE * 8];      // logits -> exp values
__device__ unsigned       g_amax [NN * 8];                 // monotone-encoded float max keys
__device__ float          g_asum [NN * 8];
__device__ float          g_rnorm[NN * 8];                 // sqrt(deg_i)/(4*asum)
__device__ int            g_cnt  [NN];                     // out-degree hist -> scatter cursor
__device__ int            g_degi [NN];                     // in-degree (by n_i)
__device__ int            g_off  [NN + 1];                 // CSR offsets by n_j
__device__ int            g_order[NE];                     // edge ids sorted by n_j

__device__ __forceinline__ float silu_f(float x) { return x / (1.0f + __expf(-x)); }

// monotone unsigned encoding of float for atomicMax
__device__ __forceinline__ unsigned fenc(float f) {
    unsigned u = __float_as_uint(f);
    return (u & 0x80000000u) ? ~u : (u | 0x80000000u);
}
__device__ __forceinline__ float fdec(unsigned k) {
    unsigned u = (k & 0x80000000u) ? (k ^ 0x80000000u) : ~k;
    return __uint_as_float(u);
}

// ---------------- C[nrows,128] = act(A[nrows,128] @ W[128,128] + bias) ----------------
__global__ void __launch_bounds__(256) node_gemm128(
    const float* __restrict__ A, const float* __restrict__ W,
    const float* __restrict__ bias, float* __restrict__ C,
    int nrows, int act)
{
    extern __shared__ float sm[];
    float* Ws = sm;          // 128*128
    float* As = sm + 16384;  // 64*128
    int tid = threadIdx.x;

    float4* Ws4 = (float4*)Ws;
    const float4* W4 = (const float4*)W;
#pragma unroll
    for (int i = 0; i < 16; i++) Ws4[tid + 256 * i] = W4[tid + 256 * i];

    int row0 = blockIdx.x * 64;
    float4* As4 = (float4*)As;
#pragma unroll
    for (int i = 0; i < 8; i++) {
        int idx = tid + 256 * i;
        int r = idx >> 5, c = idx & 31;
        float4 val = make_float4(0.f, 0.f, 0.f, 0.f);
        if (row0 + r < nrows) val = *(const float4*)(A + (size_t)(row0 + r) * 128 + c * 4);
        As4[idx] = val;
    }
    __syncthreads();

    int tx = tid & 31, ty = tid >> 5;
    int c0 = tx * 4, r0 = ty * 8;
    float acc[8][4];
#pragma unroll
    for (int i = 0; i < 8; i++) { acc[i][0] = acc[i][1] = acc[i][2] = acc[i][3] = 0.f; }

#pragma unroll 4
    for (int kk = 0; kk < 128; kk++) {
        float4 w = Ws4[kk * 32 + tx];
#pragma unroll
        for (int i = 0; i < 8; i++) {
            float a = As[(r0 + i) * 128 + kk];
            acc[i][0] = fmaf(a, w.x, acc[i][0]);
            acc[i][1] = fmaf(a, w.y, acc[i][1]);
            acc[i][2] = fmaf(a, w.z, acc[i][2]);
            acc[i][3] = fmaf(a, w.w, acc[i][3]);
        }
    }

    float4 b4 = *(const float4*)(bias + c0);
#pragma unroll
    for (int i = 0; i < 8; i++) {
        int row = row0 + r0 + i;
        if (row < nrows) {
            float4 o;
            o.x = acc[i][0] + b4.x; o.y = acc[i][1] + b4.y;
            o.z = acc[i][2] + b4.z; o.w = acc[i][3] + b4.w;
            if (act) { o.x = silu_f(o.x); o.y = silu_f(o.y); o.z = silu_f(o.z); o.w = silu_f(o.w); }
            *(float4*)(C + (size_t)row * 128 + c0) = o;
        }
    }
}

// ---------------- P[j,h,:] = v[j, h*16:(h+1)*16] @ wc[h*16:(h+1)*16, :] ----------------
__global__ void __launch_bounds__(256) p_gemm(
    const float* __restrict__ V, const float* __restrict__ WC,
    float* __restrict__ P, int nrows)
{
    __shared__ float Ws[16 * 128];
    __shared__ float As[64 * 16];
    int tid = threadIdx.x;
    int hh = blockIdx.y;

    float4* Ws4 = (float4*)Ws;
#pragma unroll
    for (int i = 0; i < 2; i++) {
        int idx = tid + 256 * i;
        Ws4[idx] = *(const float4*)(WC + (size_t)hh * 16 * 128 + idx * 4);
    }
    int row0 = blockIdx.x * 64;
    float4* As4 = (float4*)As;
    {
        int idx = tid;
        int r = idx >> 2, c = idx & 3;
        float4 val = make_float4(0.f, 0.f, 0.f, 0.f);
        if (row0 + r < nrows) val = *(const float4*)(V + (size_t)(row0 + r) * 128 + hh * 16 + c * 4);
        As4[idx] = val;
    }
    __syncthreads();

    int tx = tid & 31, ty = tid >> 5;
    int c0 = tx * 4, r0 = ty * 8;
    float acc[8][4] = {};
#pragma unroll
    for (int kk = 0; kk < 16; kk++) {
        float4 w = Ws4[kk * 32 + tx];
#pragma unroll
        for (int i = 0; i < 8; i++) {
            float a = As[(r0 + i) * 16 + kk];
            acc[i][0] = fmaf(a, w.x, acc[i][0]);
            acc[i][1] = fmaf(a, w.y, acc[i][1]);
            acc[i][2] = fmaf(a, w.z, acc[i][2]);
            acc[i][3] = fmaf(a, w.w, acc[i][3]);
        }
    }
#pragma unroll
    for (int i = 0; i < 8; i++) {
        int row = row0 + r0 + i;
        if (row < nrows)
            *(float4*)(P + (size_t)row * 1024 + hh * 128 + c0) =
                make_float4(acc[i][0], acc[i][1], acc[i][2], acc[i][3]);
    }
}

// ---------------- reset accumulators / counters ----------------
__global__ void init_kernel() {
    int i = blockIdx.x * blockDim.x + threadIdx.x;
    if (i < NN * 8) { g_amax[i] = 0u; g_asum[i] = 0.f; }
    if (i < NN)     { g_cnt[i] = 0; g_degi[i] = 0; }
}

// ---------------- histogram: out-degree by n_j, in-degree by n_i ----------------
__global__ void hist_kernel(const int* __restrict__ EI) {
    int e = blockIdx.x * blockDim.x + threadIdx.x;
    if (e < NE) {
        atomicAdd(&g_cnt[EI[e]], 1);
        atomicAdd(&g_degi[EI[NE + e]], 1);
    }
}

// ---------------- single-block exclusive scan of g_cnt -> g_off; g_cnt becomes cursor ----------------
__global__ void __launch_bounds__(1024) scan_kernel() {
    __shared__ int ssum[1024];
    int tid = threadIdx.x;
    const int CH = (NN + 1023) / 1024;  // 49
    int lo = tid * CH;
    int hi = lo + CH; if (hi > NN) hi = NN; if (lo > NN) lo = NN;
    int s = 0;
    for (int i = lo; i < hi; i++) s += g_cnt[i];
    ssum[tid] = s;
    __syncthreads();
    for (int off = 1; off < 1024; off <<= 1) {
        int v = (tid >= off) ? ssum[tid - off] : 0;
        __syncthreads();
        ssum[tid] += v;
        __syncthreads();
    }
    int run = ssum[tid] - s;   // exclusive base for this chunk
    for (int i = lo; i < hi; i++) {
        int c = g_cnt[i];
        g_off[i] = run;
        g_cnt[i] = run;        // cursor for scatter
        run += c;
    }
    if (tid == 1023) g_off[NN] = ssum[1023];
}

// ---------------- scatter edge ids into n_j-sorted order ----------------
__global__ void scatter_kernel(const int* __restrict__ EI) {
    int e = blockIdx.x * blockDim.x + threadIdx.x;
    if (e < NE) {
        int pos = atomicAdd(&g_cnt[EI[e]], 1);
        g_order[pos] = e;
    }
}

// ---------------- per-edge logits: re=silu(t@wre+bre); a=sum(q_i*k_j*re) per head ----------------
__global__ void __launch_bounds__(256) edge_logits(
    const float* __restrict__ T, const int* __restrict__ EI,
    const float* __restrict__ WRE, const float* __restrict__ BRE)
{
    extern __shared__ float sm[];
    float* Ws = sm;                         // 64*128 = 8192
    float* Ts = sm + 8192;                  // 32*64  = 2048
    float* Rs = sm + 8192 + 2048;           // 32*128 = 4096
    float* Bs = sm + 8192 + 2048 + 4096;    // 128
    int tid = threadIdx.x;

    float4* Ws4 = (float4*)Ws;
#pragma unroll
    for (int i = 0; i < 8; i++) Ws4[tid + 256 * i] = ((const float4*)WRE)[tid + 256 * i];
    if (tid < 128) Bs[tid] = BRE[tid];

    int e0 = blockIdx.x * 32;
    float4* Ts4 = (float4*)Ts;
#pragma unroll
    for (int i = 0; i < 2; i++) {
        int idx = tid + 256 * i;
        Ts4[idx] = *(const float4*)(T + (size_t)e0 * 64 + idx * 4);
    }
    __syncthreads();

    int tx = tid & 31, ty = tid >> 5;
    int c0 = tx * 4, r0 = ty * 4;
    float acc[4][4] = {};
#pragma unroll 4
    for (int kk = 0; kk < 64; kk++) {
        float4 w = Ws4[kk * 32 + tx];
#pragma unroll
        for (int i = 0; i < 4; i++) {
            float a = Ts[(r0 + i) * 64 + kk];
            acc[i][0] = fmaf(a, w.x, acc[i][0]);
            acc[i][1] = fmaf(a, w.y, acc[i][1]);
            acc[i][2] = fmaf(a, w.z, acc[i][2]);
            acc[i][3] = fmaf(a, w.w, acc[i][3]);
        }
    }
    float4 b4 = *(const float4*)(Bs + c0);
#pragma unroll
    for (int i = 0; i < 4; i++) {
        float4 o;
        o.x = silu_f(acc[i][0] + b4.x); o.y = silu_f(acc[i][1] + b4.y);
        o.z = silu_f(acc[i][2] + b4.z); o.w = silu_f(acc[i][3] + b4.w);
        *(float4*)(Rs + (r0 + i) * 128 + c0) = o;
    }
    __syncthreads();

    int lane = tx;
#pragma unroll
    for (int i = 0; i < 4; i++) {
        int el = ty * 4 + i;
        int e = e0 + el;
        int nj = EI[e];
        int ni = EI[NE + e];
        float4 q4 = *(const float4*)(g_q + (size_t)ni * 128 + lane * 4);
        float4 k4 = *(const float4*)(g_k + (size_t)nj * 128 + lane * 4);
        float4 r4 = *(const float4*)(Rs + el * 128 + lane * 4);
        float p = q4.x * k4.x * r4.x + q4.y * k4.y * r4.y
                + q4.z * k4.z * r4.z + q4.w * k4.w * r4.w;
        p += __shfl_xor_sync(0xffffffffu, p, 1);
        p += __shfl_xor_sync(0xffffffffu, p, 2);
        if ((lane & 3) == 0) {
            int hh = lane >> 2;
            g_a[(size_t)e * 8 + hh] = p;
            atomicMax(&g_amax[ni * 8 + hh], fenc(p));
        }
    }
}

// ---------------- a_exp = exp(a - amax[ni]); asum += a_exp ----------------
__global__ void edge_exp(const int* __restrict__ EI) {
    int e = blockIdx.x * blockDim.x + threadIdx.x;
    if (e >= NE) return;
    int ni = EI[NE + e];
#pragma unroll
    for (int hh = 0; hh < 8; hh++) {
        float m = fdec(g_amax[ni * 8 + hh]);
        float ex = __expf(g_a[(size_t)e * 8 + hh] - m);
        g_a[(size_t)e * 8 + hh] = ex;
        atomicAdd(&g_asum[ni * 8 + hh], ex);
    }
}

// ---------------- per-(node,head) normalization factor ----------------
__global__ void rnorm_kernel() {
    int i = blockIdx.x * blockDim.x + threadIdx.x;
    if (i >= NN * 8) return;
    float s = g_asum[i];
    float d = (float)g_degi[i >> 3];
    g_rnorm[i] = (s != 0.f) ? sqrtf(d) * 0.25f / s : 0.f;
}

// ---------------- warp-per-source-node output: P[j] in regs, stream out-edges ----------------
__global__ void __launch_bounds__(256) edge_out_sorted(
    const int* __restrict__ EI, const float* __restrict__ BC, float* __restrict__ OUT)
{
    int j = blockIdx.x * 8 + (threadIdx.x >> 5);
    int lane = threadIdx.x & 31;
    if (j >= NN) return;
    int s = g_off[j], e_end = g_off[j + 1];
    if (s == e_end) return;

    const float* Pj = g_P + (size_t)j * 1024;
    float4 p[8];
#pragma unroll
    for (int h = 0; h < 8; h++)
        p[h] = *(const float4*)(Pj + h * 128 + lane * 4);
    float4 b4 = *(const float4*)(BC + lane * 4);

    for (int x = s; x < e_end; x++) {
        int e = g_order[x];
        int ni = EI[NE + e];
        float w = 0.f;
        if (lane < 8) w = g_a[(size_t)e * 8 + lane] * g_rnorm[ni * 8 + lane];

        float4 acc = b4;
#pragma unroll
        for (int h = 0; h < 8; h++) {
            float wh = __shfl_sync(0xffffffffu, w, h);
            acc.x = fmaf(wh, p[h].x, acc.x);
            acc.y = fmaf(wh, p[h].y, acc.y);
            acc.z = fmaf(wh, p[h].z, acc.z);
            acc.w = fmaf(wh, p[h].w, acc.w);
        }
        *(float4*)(OUT + (size_t)e * 128 + lane * 4) = acc;
    }
}

// ---------------- launch ----------------
extern "C" void kernel_launch(void* const* d_in, const int* in_sizes, int n_in,
                              void* d_out, int out_size)
{
    const float* h   = (const float*)d_in[0];
    const float* t   = (const float*)d_in[1];
    const int*   ei  = (const int*)  d_in[2];
    const float* wq  = (const float*)d_in[3];
    const float* bq  = (const float*)d_in[4];
    const float* wk  = (const float*)d_in[5];
    const float* bk  = (const float*)d_in[6];
    const float* wre = (const float*)d_in[7];
    const float* bre = (const float*)d_in[8];
    const float* mw1 = (const float*)d_in[9];
    const float* mb1 = (const float*)d_in[10];
    const float* mw2 = (const float*)d_in[11];
    const float* mb2 = (const float*)d_in[12];
    const float* wc  = (const float*)d_in[13];
    const float* bc  = (const float*)d_in[14];
    float* out = (float*)d_out;

    (void)in_sizes; (void)n_in; (void)out_size;

    cudaFuncSetAttribute(node_gemm128, cudaFuncAttributeMaxDynamicSharedMemorySize, 98304);
    cudaFuncSetAttribute(edge_logits,  cudaFuncAttributeMaxDynamicSharedMemorySize, 57856);

    float *q_p, *k_p, *t1_p, *v_p, *P_p;
    cudaGetSymbolAddress((void**)&q_p,  g_q);
    cudaGetSymbolAddress((void**)&k_p,  g_k);
    cudaGetSymbolAddress((void**)&t1_p, g_t1);
    cudaGetSymbolAddress((void**)&v_p,  g_v);
    cudaGetSymbolAddress((void**)&P_p,  g_P);

    init_kernel<<<(NN * 8 + 255) / 256, 256>>>();
    hist_kernel<<<(NE + 255) / 256, 256>>>(ei);
    scan_kernel<<<1, 1024>>>();
    scatter_kernel<<<(NE + 255) / 256, 256>>>(ei);

    int nblk = (NN + 63) / 64;  // 782
    node_gemm128<<<nblk, 256, 98304>>>(h,    wq,  bq,  q_p,  NN, 0);
    node_gemm128<<<nblk, 256, 98304>>>(h,    wk,  bk,  k_p,  NN, 0);
    node_gemm128<<<nblk, 256, 98304>>>(h,    mw1, mb1, t1_p, NN, 1);  // silu
    node_gemm128<<<nblk, 256, 98304>>>(t1_p, mw2, mb2, v_p,  NN, 0);

    dim3 pg(nblk, 8);
    p_gemm<<<pg, 256>>>(v_p, wc, P_p, NN);

    edge_logits<<<NE / 32, 256, 57856>>>(t, ei, wre, bre);
    edge_exp<<<(NE + 255) / 256, 256>>>(ei);
    rnorm_kernel<<<(NN * 8 + 255) / 256, 256>>>();
    edge_out_sorted<<<(NN + 7) / 8, 256>>>(ei, bc, out);
}

// round 4
// speedup vs baseline: 1.0256x; 1.0234x over previous
#include <cuda_runtime.h>
#include <cuda_bf16.h>
#include <math.h>
#include <cstdint>

#define NN 50000
#define NE 400000

// =============== mma.sync helpers (base sm_103 target legal) ===============
__device__ __forceinline__ uint32_t smem_to_u32(const void* p) {
    uint32_t a;
    asm("{ .reg .u64 t; cvta.to.shared.u64 t, %1; cvt.u32.u64 %0, t; }" : "=r"(a) : "l"(p));
    return a;
}
__device__ __forceinline__ void ldsm_x4(uint32_t addr, uint32_t* r) {
    asm volatile("ldmatrix.sync.aligned.m8n8.x4.shared.b16 {%0,%1,%2,%3}, [%4];"
        : "=r"(r[0]), "=r"(r[1]), "=r"(r[2]), "=r"(r[3]) : "r"(addr));
}
__device__ __forceinline__ void mma_bf16(float* d, const uint32_t* a, const uint32_t* b) {
    asm volatile("mma.sync.aligned.m16n8k16.row.col.f32.bf16.bf16.f32 "
        "{%0,%1,%2,%3}, {%4,%5,%6,%7}, {%8,%9}, {%0,%1,%2,%3};"
        : "+f"(d[0]), "+f"(d[1]), "+f"(d[2]), "+f"(d[3])
        : "r"(a[0]), "r"(a[1]), "r"(a[2]), "r"(a[3]), "r"(b[0]), "r"(b[1]));
}
// lane address for A-fragment tiles (x4: rowsL/kL, rowsU/kL, rowsL/kU, rowsU/kU)
__device__ __forceinline__ uint32_t a_lane_addr(uint32_t base, int R, int lane, int stride) {
    int t = lane >> 3;
    int row = R + (lane & 7) + (t & 1) * 8;
    int k8  = (t >> 1) * 8;
    return base + row * stride + k8 * 2;
}
// lane address for B-fragment tiles from BT[n][k] (x4: nL/kL, nL/kU, nU/kL, nU/kU)
__device__ __forceinline__ uint32_t b_lane_addr(uint32_t base, int lane, int stride) {
    int t = lane >> 3;
    int n  = (lane & 7) + (t >> 1) * 8;
    int k8 = (t & 1) * 8;
    return base + n * stride + k8 * 2;
}
// 3-pass split-bf16 GEMM: acc[16][4] covers 16 x (m16n8); KSTEPS k-chunks of 16.
template<int KSTEPS>
__device__ __forceinline__ void warp_gemm(
    uint32_t aH, uint32_t aL, uint32_t bH, uint32_t bL, int bstride, float (*acc)[4])
{
#pragma unroll
    for (int ks = 0; ks < KSTEPS; ks++) {
        uint32_t rah[4], ral[4];
        ldsm_x4(aH + ks * 32, rah);
        ldsm_x4(aL + ks * 32, ral);
#pragma unroll
        for (int nbp = 0; nbp < 8; nbp++) {
            uint32_t bh[4], bl[4];
            ldsm_x4(bH + nbp * 16 * bstride + ks * 32, bh);
            ldsm_x4(bL + nbp * 16 * bstride + ks * 32, bl);
            mma_bf16(acc[2 * nbp],     rah, bh);
            mma_bf16(acc[2 * nbp],     rah, bl);
            mma_bf16(acc[2 * nbp],     ral, bh);
            mma_bf16(acc[2 * nbp + 1], rah, bh + 2);
            mma_bf16(acc[2 * nbp + 1], rah, bl + 2);
            mma_bf16(acc[2 * nbp + 1], ral, bh + 2);
        }
    }
}

__device__ __forceinline__ float silu_f(float x) { return x / (1.0f + __expf(-x)); }
__device__ __forceinline__ unsigned fenc(float f) {
    unsigned u = __float_as_uint(f);
    return (u & 0x80000000u) ? ~u : (u | 0x80000000u);
}
__device__ __forceinline__ float fdec(unsigned k) {
    unsigned u = (k & 0x80000000u) ? (k ^ 0x80000000u) : ~k;
    return __uint_as_float(u);
}
__device__ __forceinline__ void split2(float x0, float x1, uint32_t& hi, uint32_t& lo) {
    __nv_bfloat16 h0 = __float2bfloat16(x0), h1 = __float2bfloat16(x1);
    __nv_bfloat16 l0 = __float2bfloat16(x0 - __bfloat162float(h0));
    __nv_bfloat16 l1 = __float2bfloat16(x1 - __bfloat162float(h1));
    __nv_bfloat162 H; H.x = h0; H.y = h1;
    __nv_bfloat162 L; L.x = l0; L.y = l1;
    hi = *(uint32_t*)&H; lo = *(uint32_t*)&L;
}

// =============== scratch globals ===============
__device__ __align__(16) float g_q [NN * 128];
__device__ __align__(16) float g_k [NN * 128];
__device__ __align__(16) float g_P [(size_t)NN * 1024];
__device__ __align__(16) float g_a [(size_t)NE * 8];
__device__ unsigned       g_amax [NN * 8];
__device__ float          g_asum [NN * 8];
__device__ float          g_rnorm[NN * 8];
__device__ int            g_cnt  [NN];
__device__ int            g_degi [NN];
__device__ int            g_off  [NN + 1];
__device__ int            g_order[NE];
// padded BT images: [n][k], row strides 136 / 72 / 24 elems
__device__ __align__(16) __nv_bfloat16 g_wimg [4][2][128 * 136];
__device__ __align__(16) __nv_bfloat16 g_wreimg[2][128 * 72];
__device__ __align__(16) __nv_bfloat16 g_wcimg [8][2][128 * 24];

// =============== weight prep ===============
__global__ void prep_w128(const float* __restrict__ wq, const float* __restrict__ wk,
                          const float* __restrict__ mw1, const float* __restrict__ mw2) {
    const float* W = (blockIdx.x == 0) ? wq : (blockIdx.x == 1) ? wk : (blockIdx.x == 2) ? mw1 : mw2;
    for (int idx = threadIdx.x; idx < 16384; idx += blockDim.x) {
        int k = idx >> 7, n = idx & 127;
        float w = W[k * 128 + n];
        __nv_bfloat16 h = __float2bfloat16(w);
        __nv_bfloat16 l = __float2bfloat16(w - __bfloat162float(h));
        g_wimg[blockIdx.x][0][n * 136 + k] = h;
        g_wimg[blockIdx.x][1][n * 136 + k] = l;
    }
}
__global__ void prep_wre(const float* __restrict__ wre) {
    for (int idx = threadIdx.x; idx < 8192; idx += blockDim.x) {
        int k = idx >> 7, n = idx & 127;           // k < 64
        float w = wre[k * 128 + n];
        __nv_bfloat16 h = __float2bfloat16(w);
        __nv_bfloat16 l = __float2bfloat16(w - __bfloat162float(h));
        g_wreimg[0][n * 72 + k] = h;
        g_wreimg[1][n * 72 + k] = l;
    }
}
__global__ void prep_wc(const float* __restrict__ wc) {
    int hh = blockIdx.x;
    for (int idx = threadIdx.x; idx < 2048; idx += blockDim.x) {
        int n = idx >> 4, k = idx & 15;
        float w = wc[(hh * 16 + k) * 128 + n];
        __nv_bfloat16 h = __float2bfloat16(w);
        __nv_bfloat16 l = __float2bfloat16(w - __bfloat162float(h));
        g_wcimg[hh][0][n * 24 + k] = h;
        g_wcimg[hh][1][n * 24 + k] = l;
    }
}

// =============== fused node kernel: q,k,t1,v,P — all tensor-core ===============
#define NB_BIAS 0
#define NB_AH   2048
#define NB_AL   (NB_AH + 34816)
#define NB_W    (NB_AL + 34816)          // 139264-byte weight region
#define NODE_SMEM (NB_W + 139264)        // 210944

__global__ void __launch_bounds__(256) node_fused_mma(
    const float* __restrict__ H,
    const float* __restrict__ bq, const float* __restrict__ bk,
    const float* __restrict__ mb1, const float* __restrict__ mb2,
    float* __restrict__ Q, float* __restrict__ K, float* __restrict__ P, int nrows)
{
    extern __shared__ char smem[];
    uint32_t sb = smem_to_u32(smem);
    float* smb = (float*)(smem + NB_BIAS);
    int tid = threadIdx.x, wid = tid >> 5, lane = tid & 31;
    int row0 = blockIdx.x * 128;
    int R = wid * 16;
    int g = lane >> 2, tig = lane & 3;

    // biases
    if (tid < 128) { smb[tid] = bq[tid]; smb[128 + tid] = bk[tid]; }
    else { int t2 = tid - 128; smb[256 + t2] = mb1[t2]; smb[384 + t2] = mb2[t2]; }

    // A = h tile split
#pragma unroll
    for (int it = 0; it < 16; it++) {
        int idx = it * 256 + tid;
        int r = idx >> 5, c4 = (idx & 31) * 4;
        float4 x = make_float4(0.f, 0.f, 0.f, 0.f);
        if (row0 + r < nrows) x = *(const float4*)(H + (size_t)(row0 + r) * 128 + c4);
        uint32_t h0, l0, h1, l1;
        split2(x.x, x.y, h0, l0);
        split2(x.z, x.w, h1, l1);
        uint32_t o = (uint32_t)(r * 272 + c4 * 2);
        asm volatile("st.shared.v2.b32 [%0], {%1, %2};" :: "r"(sb + NB_AH + o), "r"(h0), "r"(h1));
        asm volatile("st.shared.v2.b32 [%0], {%1, %2};" :: "r"(sb + NB_AL + o), "r"(l0), "r"(l1));
    }
    // W <- wq,wk images (hi+lo each 34816B; 8704 uint4 total)
    {
        const uint4* s = (const uint4*)(&g_wimg[0][0][0]);
        uint4* d = (uint4*)(smem + NB_W);
#pragma unroll
        for (int i = 0; i < 34; i++) d[tid + 256 * i] = s[tid + 256 * i];
    }
    __syncthreads();

    uint32_t aH = a_lane_addr(sb + NB_AH, R, lane, 272);
    uint32_t aL = a_lane_addr(sb + NB_AL, R, lane, 272);

    float acc[16][4];
    int rlo = row0 + R + g, rhi = rlo + 8;

    // ---- q ----
#pragma unroll
    for (int i = 0; i < 16; i++) { acc[i][0] = acc[i][1] = acc[i][2] = acc[i][3] = 0.f; }
    warp_gemm<8>(aH, aL, b_lane_addr(sb + NB_W, lane, 272), b_lane_addr(sb + NB_W + 34816, lane, 272), 272, acc);
#pragma unroll
    for (int nb = 0; nb < 16; nb++) {
        int c = nb * 8 + tig * 2;
        if (rlo < nrows) *(float2*)(Q + (size_t)rlo * 128 + c) = make_float2(acc[nb][0] + smb[c], acc[nb][1] + smb[c + 1]);
        if (rhi < nrows) *(float2*)(Q + (size_t)rhi * 128 + c) = make_float2(acc[nb][2] + smb[c], acc[nb][3] + smb[c + 1]);
    }
    // ---- k ----
#pragma unroll
    for (int i = 0; i < 16; i++) { acc[i][0] = acc[i][1] = acc[i][2] = acc[i][3] = 0.f; }
    warp_gemm<8>(aH, aL, b_lane_addr(sb + NB_W + 69632, lane, 272), b_lane_addr(sb + NB_W + 104448, lane, 272), 272, acc);
#pragma unroll
    for (int nb = 0; nb < 16; nb++) {
        int c = nb * 8 + tig * 2;
        if (rlo < nrows) *(float2*)(K + (size_t)rlo * 128 + c) = make_float2(acc[nb][0] + smb[128 + c], acc[nb][1] + smb[128 + c + 1]);
        if (rhi < nrows) *(float2*)(K + (size_t)rhi * 128 + c) = make_float2(acc[nb][2] + smb[128 + c], acc[nb][3] + smb[128 + c + 1]);
    }
    __syncthreads();
    // W <- mw1,mw2
    {
        const uint4* s = (const uint4*)(&g_wimg[2][0][0]);
        uint4* d = (uint4*)(smem + NB_W);
#pragma unroll
        for (int i = 0; i < 34; i++) d[tid + 256 * i] = s[tid + 256 * i];
    }
    __syncthreads();

    // ---- t1 = silu(h@mw1 + mb1) ----
#pragma unroll
    for (int i = 0; i < 16; i++) { acc[i][0] = acc[i][1] = acc[i][2] = acc[i][3] = 0.f; }
    warp_gemm<8>(aH, aL, b_lane_addr(sb + NB_W, lane, 272), b_lane_addr(sb + NB_W + 34816, lane, 272), 272, acc);
    __syncthreads();   // everyone done reading A
#pragma unroll
    for (int nb = 0; nb < 16; nb++) {
        int c = nb * 8 + tig * 2;
        uint32_t hi, lo;
        split2(silu_f(acc[nb][0] + smb[256 + c]), silu_f(acc[nb][1] + smb[256 + c + 1]), hi, lo);
        uint32_t o = (uint32_t)((R + g) * 272 + c * 2);
        asm volatile("st.shared.b32 [%0], %1;" :: "r"(sb + NB_AH + o), "r"(hi));
        asm volatile("st.shared.b32 [%0], %1;" :: "r"(sb + NB_AL + o), "r"(lo));
        split2(silu_f(acc[nb][2] + smb[256 + c]), silu_f(acc[nb][3] + smb[256 + c + 1]), hi, lo);
        o = (uint32_t)((R + g + 8) * 272 + c * 2);
        asm volatile("st.shared.b32 [%0], %1;" :: "r"(sb + NB_AH + o), "r"(hi));
        asm volatile("st.shared.b32 [%0], %1;" :: "r"(sb + NB_AL + o), "r"(lo));
    }
    __syncthreads();

    // ---- v = t1@mw2 + mb2 ----
#pragma unroll
    for (int i = 0; i < 16; i++) { acc[i][0] = acc[i][1] = acc[i][2] = acc[i][3] = 0.f; }
    warp_gemm<8>(aH, aL, b_lane_addr(sb + NB_W + 69632, lane, 272), b_lane_addr(sb + NB_W + 104448, lane, 272), 272, acc);
    __syncthreads();   // done reading A(t1) and W
    // write v split into A; copy WC images into W
#pragma unroll
    for (int nb = 0; nb < 16; nb++) {
        int c = nb * 8 + tig * 2;
        uint32_t hi, lo;
        split2(acc[nb][0] + smb[384 + c], acc[nb][1] + smb[384 + c + 1], hi, lo);
        uint32_t o = (uint32_t)((R + g) * 272 + c * 2);
        asm volatile("st.shared.b32 [%0], %1;" :: "r"(sb + NB_AH + o), "r"(hi));
        asm volatile("st.shared.b32 [%0], %1;" :: "r"(sb + NB_AL + o), "r"(lo));
        split2(acc[nb][2] + smb[384 + c], acc[nb][3] + smb[384 + c + 1], hi, lo);
        o = (uint32_t)((R + g + 8) * 272 + c * 2);
        asm volatile("st.shared.b32 [%0], %1;" :: "r"(sb + NB_AH + o), "r"(hi));
        asm volatile("st.shared.b32 [%0], %1;" :: "r"(sb + NB_AL + o), "r"(lo));
    }
    {
        // 8 heads x (hi 6144B + lo 6144B) = 98304B = 6144 uint4
        const uint4* s = (const uint4*)(&g_wcimg[0][0][0]);
        uint4* d = (uint4*)(smem + NB_W);
#pragma unroll
        for (int i = 0; i < 24; i++) d[tid + 256 * i] = s[tid + 256 * i];
    }
    __syncthreads();

    // ---- P per head: P_h = v[:, h*16:(h+1)*16] @ wc_h ----
#pragma unroll
    for (int hh = 0; hh < 8; hh++) {
#pragma unroll
        for (int i = 0; i < 16; i++) { acc[i][0] = acc[i][1] = acc[i][2] = acc[i][3] = 0.f; }
        warp_gemm<1>(aH + hh * 32, aL + hh * 32,
                     b_lane_addr(sb + NB_W + hh * 12288, lane, 48),
                     b_lane_addr(sb + NB_W + hh * 12288 + 6144, lane, 48), 48, acc);
#pragma unroll
        for (int nb = 0; nb < 16; nb++) {
            int c = hh * 128 + nb * 8 + tig * 2;
            if (rlo < nrows) *(float2*)(P + (size_t)rlo * 1024 + c) = make_float2(acc[nb][0], acc[nb][1]);
            if (rhi < nrows) *(float2*)(P + (size_t)rhi * 1024 + c) = make_float2(acc[nb][2], acc[nb][3]);
        }
    }
}

// =============== edge logits: re GEMM (tensor) + gather/reduce ===============
#define EB_BIAS 0
#define EB_TH   512
#define EB_TL   (EB_TH + 18432)
#define EB_WH   (EB_TL + 18432)
#define EB_WL   (EB_WH + 18432)
#define EB_RS   (EB_WL + 18432)
#define EDGE_SMEM (EB_RS + 65536)   // 139776

__global__ void __launch_bounds__(256) edge_logits_mma(
    const float* __restrict__ T, const int* __restrict__ EI, const float* __restrict__ BRE)
{
    extern __shared__ char smem[];
    uint32_t sb = smem_to_u32(smem);
    float* smb = (float*)(smem + EB_BIAS);
    float* Rs  = (float*)(smem + EB_RS);
    int tid = threadIdx.x, wid = tid >> 5, lane = tid & 31;
    int e0 = blockIdx.x * 128;
    int R = wid * 16;
    int g = lane >> 2, tig = lane & 3;

    if (tid < 128) smb[tid] = BRE[tid];
    // wre images copy: 2 x 18432B = 2304 uint4
    {
        const uint4* s = (const uint4*)(&g_wreimg[0][0]);
        uint4* d = (uint4*)(smem + EB_WH);
#pragma unroll
        for (int i = 0; i < 9; i++) d[tid + 256 * i] = s[tid + 256 * i];
    }
    // T tile split: 128 x 64 f32 = 2048 float4
#pragma unroll
    for (int it = 0; it < 8; it++) {
        int idx = it * 256 + tid;
        int r = idx >> 4, c4 = (idx & 15) * 4;
        float4 x = *(const float4*)(T + (size_t)(e0 + r) * 64 + c4);
        uint32_t h0, l0, h1, l1;
        split2(x.x, x.y, h0, l0);
        split2(x.z, x.w, h1, l1);
        uint32_t o = (uint32_t)(r * 144 + c4 * 2);
        asm volatile("st.shared.v2.b32 [%0], {%1, %2};" :: "r"(sb + EB_TH + o), "r"(h0), "r"(h1));
        asm volatile("st.shared.v2.b32 [%0], {%1, %2};" :: "r"(sb + EB_TL + o), "r"(l0), "r"(l1));
    }
    __syncthreads();

    float acc[16][4];
#pragma unroll
    for (int i = 0; i < 16; i++) { acc[i][0] = acc[i][1] = acc[i][2] = acc[i][3] = 0.f; }
    warp_gemm<4>(a_lane_addr(sb + EB_TH, R, lane, 144), a_lane_addr(sb + EB_TL, R, lane, 144),
                 b_lane_addr(sb + EB_WH, lane, 144),    b_lane_addr(sb + EB_WL, lane, 144), 144, acc);

    // epilogue: silu(acc + bias) -> Rs
#pragma unroll
    for (int nb = 0; nb < 16; nb++) {
        int c = nb * 8 + tig * 2;
        float b0 = smb[c], b1 = smb[c + 1];
        *(float2*)(Rs + (R + g) * 128 + c)     = make_float2(silu_f(acc[nb][0] + b0), silu_f(acc[nb][1] + b1));
        *(float2*)(Rs + (R + g + 8) * 128 + c) = make_float2(silu_f(acc[nb][2] + b0), silu_f(acc[nb][3] + b1));
    }
    __syncthreads();

    // gather phase: 16 edges per warp
#pragma unroll
    for (int i = 0; i < 16; i++) {
        int el = wid * 16 + i;
        int e = e0 + el;
        int nj = EI[e];
        int ni = EI[NE + e];
        float4 q4 = *(const float4*)(g_q + (size_t)ni * 128 + lane * 4);
        float4 k4 = *(const float4*)(g_k + (size_t)nj * 128 + lane * 4);
        float4 r4 = *(const float4*)(Rs + el * 128 + lane * 4);
        float p = q4.x * k4.x * r4.x + q4.y * k4.y * r4.y
                + q4.z * k4.z * r4.z + q4.w * k4.w * r4.w;
        p += __shfl_xor_sync(0xffffffffu, p, 1);
        p += __shfl_xor_sync(0xffffffffu, p, 2);
        if ((lane & 3) == 0) {
            int hh = lane >> 2;
            g_a[(size_t)e * 8 + hh] = p;
            atomicMax(&g_amax[ni * 8 + hh], fenc(p));
        }
    }
}

// =============== bookkeeping (unchanged) ===============
__global__ void init_kernel() {
    int i = blockIdx.x * blockDim.x + threadIdx.x;
    if (i < NN * 8) { g_amax[i] = 0u; g_asum[i] = 0.f; }
    if (i < NN)     { g_cnt[i] = 0; g_degi[i] = 0; }
}
__global__ void hist_kernel(const int* __restrict__ EI) {
    int e = blockIdx.x * blockDim.x + threadIdx.x;
    if (e < NE) {
        atomicAdd(&g_cnt[EI[e]], 1);
        atomicAdd(&g_degi[EI[NE + e]], 1);
    }
}
__global__ void __launch_bounds__(1024) scan_kernel() {
    __shared__ int ssum[1024];
    int tid = threadIdx.x;
    const int CH = (NN + 1023) / 1024;
    int lo = tid * CH;
    int hi = lo + CH; if (hi > NN) hi = NN; if (lo > NN) lo = NN;
    int s = 0;
    for (int i = lo; i < hi; i++) s += g_cnt[i];
    ssum[tid] = s;
    __syncthreads();
    for (int off = 1; off < 1024; off <<= 1) {
        int v = (tid >= off) ? ssum[tid - off] : 0;
        __syncthreads();
        ssum[tid] += v;
        __syncthreads();
    }
    int run = ssum[tid] - s;
    for (int i = lo; i < hi; i++) {
        int c = g_cnt[i];
        g_off[i] = run;
        g_cnt[i] = run;
        run += c;
    }
    if (tid == 1023) g_off[NN] = ssum[1023];
}
__global__ void scatter_kernel(const int* __restrict__ EI) {
    int e = blockIdx.x * blockDim.x + threadIdx.x;
    if (e < NE) {
        int pos = atomicAdd(&g_cnt[EI[e]], 1);
        g_order[pos] = e;
    }
}
__global__ void edge_exp(const int* __restrict__ EI) {
    int e = blockIdx.x * blockDim.x + threadIdx.x;
    if (e >= NE) return;
    int ni = EI[NE + e];
#pragma unroll
    for (int hh = 0; hh < 8; hh++) {
        float m = fdec(g_amax[ni * 8 + hh]);
        float ex = __expf(g_a[(size_t)e * 8 + hh] - m);
        g_a[(size_t)e * 8 + hh] = ex;
        atomicAdd(&g_asum[ni * 8 + hh], ex);
    }
}
__global__ void rnorm_kernel() {
    int i = blockIdx.x * blockDim.x + threadIdx.x;
    if (i >= NN * 8) return;
    float s = g_asum[i];
    float d = (float)g_degi[i >> 3];
    g_rnorm[i] = (s != 0.f) ? sqrtf(d) * 0.25f / s : 0.f;
}
__global__ void __launch_bounds__(256) edge_out_sorted(
    const int* __restrict__ EI, const float* __restrict__ BC, float* __restrict__ OUT)
{
    int j = blockIdx.x * 8 + (threadIdx.x >> 5);
    int lane = threadIdx.x & 31;
    if (j >= NN) return;
    int s = g_off[j], e_end = g_off[j + 1];
    if (s == e_end) return;

    const float* Pj = g_P + (size_t)j * 1024;
    float4 p[8];
#pragma unroll
    for (int h = 0; h < 8; h++)
        p[h] = *(const float4*)(Pj + h * 128 + lane * 4);
    float4 b4 = *(const float4*)(BC + lane * 4);

    for (int x = s; x < e_end; x++) {
        int e = g_order[x];
        int ni = EI[NE + e];
        float w = 0.f;
        if (lane < 8) w = g_a[(size_t)e * 8 + lane] * g_rnorm[ni * 8 + lane];

        float4 acc = b4;
#pragma unroll
        for (int h = 0; h < 8; h++) {
            float wh = __shfl_sync(0xffffffffu, w, h);
            acc.x = fmaf(wh, p[h].x, acc.x);
            acc.y = fmaf(wh, p[h].y, acc.y);
            acc.z = fmaf(wh, p[h].z, acc.z);
            acc.w = fmaf(wh, p[h].w, acc.w);
        }
        *(float4*)(OUT + (size_t)e * 128 + lane * 4) = acc;
    }
}

// =============== launch ===============
extern "C" void kernel_launch(void* const* d_in, const int* in_sizes, int n_in,
                              void* d_out, int out_size)
{
    const float* h   = (const float*)d_in[0];
    const float* t   = (const float*)d_in[1];
    const int*   ei  = (const int*)  d_in[2];
    const float* wq  = (const float*)d_in[3];
    const float* bq  = (const float*)d_in[4];
    const float* wk  = (const float*)d_in[5];
    const float* bk  = (const float*)d_in[6];
    const float* wre = (const float*)d_in[7];
    const float* bre = (const float*)d_in[8];
    const float* mw1 = (const float*)d_in[9];
    const float* mb1 = (const float*)d_in[10];
    const float* mw2 = (const float*)d_in[11];
    const float* mb2 = (const float*)d_in[12];
    const float* wc  = (const float*)d_in[13];
    const float* bc  = (const float*)d_in[14];
    float* out = (float*)d_out;

    (void)in_sizes; (void)n_in; (void)out_size;

    cudaFuncSetAttribute(node_fused_mma,  cudaFuncAttributeMaxDynamicSharedMemorySize, NODE_SMEM);
    cudaFuncSetAttribute(edge_logits_mma, cudaFuncAttributeMaxDynamicSharedMemorySize, EDGE_SMEM);

    float *q_p, *k_p, *P_p;
    cudaGetSymbolAddress((void**)&q_p, g_q);
    cudaGetSymbolAddress((void**)&k_p, g_k);
    cudaGetSymbolAddress((void**)&P_p, g_P);

    init_kernel<<<(NN * 8 + 255) / 256, 256>>>();
    hist_kernel<<<(NE + 255) / 256, 256>>>(ei);
    scan_kernel<<<1, 1024>>>();
    scatter_kernel<<<(NE + 255) / 256, 256>>>(ei);

    prep_w128<<<4, 256>>>(wq, wk, mw1, mw2);
    prep_wre<<<1, 256>>>(wre);
    prep_wc<<<8, 256>>>(wc);

    node_fused_mma<<<(NN + 127) / 128, 256, NODE_SMEM>>>(h, bq, bk, mb1, mb2, q_p, k_p, P_p, NN);

    edge_logits_mma<<<NE / 128, 256, EDGE_SMEM>>>(t, ei, bre);
    edge_exp<<<(NE + 255) / 256, 256>>>(ei);
    rnorm_kernel<<<(NN * 8 + 255) / 256, 256>>>();
    edge_out_sorted<<<(NN + 7) / 8, 256>>>(ei, bc, out);
}

// round 5
// speedup vs baseline: 1.2539x; 1.2225x over previous
#include <cuda_runtime.h>
#include <cuda_bf16.h>
#include <math.h>
#include <cstdint>

#define NN 50000
#define NE 400000

// =============== mma.sync helpers ===============
__device__ __forceinline__ uint32_t smem_to_u32(const void* p) {
    uint32_t a;
    asm("{ .reg .u64 t; cvta.to.shared.u64 t, %1; cvt.u32.u64 %0, t; }" : "=r"(a) : "l"(p));
    return a;
}
__device__ __forceinline__ void ldsm_x4(uint32_t addr, uint32_t* r) {
    asm volatile("ldmatrix.sync.aligned.m8n8.x4.shared.b16 {%0,%1,%2,%3}, [%4];"
        : "=r"(r[0]), "=r"(r[1]), "=r"(r[2]), "=r"(r[3]) : "r"(addr));
}
__device__ __forceinline__ void mma_bf16(float* d, const uint32_t* a, const uint32_t* b) {
    asm volatile("mma.sync.aligned.m16n8k16.row.col.f32.bf16.bf16.f32 "
        "{%0,%1,%2,%3}, {%4,%5,%6,%7}, {%8,%9}, {%0,%1,%2,%3};"
        : "+f"(d[0]), "+f"(d[1]), "+f"(d[2]), "+f"(d[3])
        : "r"(a[0]), "r"(a[1]), "r"(a[2]), "r"(a[3]), "r"(b[0]), "r"(b[1]));
}
__device__ __forceinline__ uint32_t a_lane_addr(uint32_t base, int R, int lane, int stride) {
    int t = lane >> 3;
    int row = R + (lane & 7) + (t & 1) * 8;
    int k8  = (t >> 1) * 8;
    return base + row * stride + k8 * 2;
}
__device__ __forceinline__ uint32_t b_lane_addr(uint32_t base, int lane, int stride) {
    int t = lane >> 3;
    int n  = (lane & 7) + (t >> 1) * 8;
    int k8 = (t & 1) * 8;
    return base + n * stride + k8 * 2;
}
template<int KSTEPS>
__device__ __forceinline__ void warp_gemm(
    uint32_t aH, uint32_t aL, uint32_t bH, uint32_t bL, int bstride, float (*acc)[4])
{
#pragma unroll
    for (int ks = 0; ks < KSTEPS; ks++) {
        uint32_t rah[4], ral[4];
        ldsm_x4(aH + ks * 32, rah);
        ldsm_x4(aL + ks * 32, ral);
#pragma unroll
        for (int nbp = 0; nbp < 8; nbp++) {
            uint32_t bh[4], bl[4];
            ldsm_x4(bH + nbp * 16 * bstride + ks * 32, bh);
            ldsm_x4(bL + nbp * 16 * bstride + ks * 32, bl);
            mma_bf16(acc[2 * nbp],     rah, bh);
            mma_bf16(acc[2 * nbp],     rah, bl);
            mma_bf16(acc[2 * nbp],     ral, bh);
            mma_bf16(acc[2 * nbp + 1], rah, bh + 2);
            mma_bf16(acc[2 * nbp + 1], rah, bl + 2);
            mma_bf16(acc[2 * nbp + 1], ral, bh + 2);
        }
    }
}

__device__ __forceinline__ float silu_f(float x) { return x / (1.0f + __expf(-x)); }
__device__ __forceinline__ void split2(float x0, float x1, uint32_t& hi, uint32_t& lo) {
    __nv_bfloat16 h0 = __float2bfloat16(x0), h1 = __float2bfloat16(x1);
    __nv_bfloat16 l0 = __float2bfloat16(x0 - __bfloat162float(h0));
    __nv_bfloat16 l1 = __float2bfloat16(x1 - __bfloat162float(h1));
    __nv_bfloat162 H; H.x = h0; H.y = h1;
    __nv_bfloat162 L; L.x = l0; L.y = l1;
    hi = *(uint32_t*)&H; lo = *(uint32_t*)&L;
}

// =============== scratch globals ===============
__device__ __align__(16) float g_q [NN * 128];
__device__ __align__(16) float g_k [NN * 128];
__device__ __align__(16) float g_P [(size_t)NN * 1024];
__device__ __align__(16) float g_a [(size_t)NE * 8];   // logits -> normalized weights
__device__ int g_cnt  [NN];
__device__ int g_cntI [NN];
__device__ int g_off  [NN + 1];   // CSR by n_j
__device__ int g_offI [NN + 1];   // CSR by n_i
__device__ int g_order [NE];
__device__ int g_orderI[NE];
__device__ __align__(16) __nv_bfloat16 g_wimg [4][2][128 * 136];
__device__ __align__(16) __nv_bfloat16 g_wreimg[2][128 * 72];
__device__ __align__(16) __nv_bfloat16 g_wcimg [8][2][128 * 24];

// =============== weight prep (chip-wide grids) ===============
__global__ void prep_w128(const float* __restrict__ wq, const float* __restrict__ wk,
                          const float* __restrict__ mw1, const float* __restrict__ mw2) {
    int gid = blockIdx.x * blockDim.x + threadIdx.x;     // 65536
    int m = gid >> 14, idx = gid & 16383;
    const float* W = (m == 0) ? wq : (m == 1) ? wk : (m == 2) ? mw1 : mw2;
    int k = idx >> 7, n = idx & 127;
    float w = W[k * 128 + n];
    __nv_bfloat16 h = __float2bfloat16(w);
    __nv_bfloat16 l = __float2bfloat16(w - __bfloat162float(h));
    g_wimg[m][0][n * 136 + k] = h;
    g_wimg[m][1][n * 136 + k] = l;
}
__global__ void prep_wre(const float* __restrict__ wre) {
    int idx = blockIdx.x * blockDim.x + threadIdx.x;     // 8192
    int k = idx >> 7, n = idx & 127;
    float w = wre[k * 128 + n];
    __nv_bfloat16 h = __float2bfloat16(w);
    __nv_bfloat16 l = __float2bfloat16(w - __bfloat162float(h));
    g_wreimg[0][n * 72 + k] = h;
    g_wreimg[1][n * 72 + k] = l;
}
__global__ void prep_wc(const float* __restrict__ wc) {
    int gid = blockIdx.x * blockDim.x + threadIdx.x;     // 16384
    int hh = gid >> 11, idx = gid & 2047;
    int n = idx >> 4, k = idx & 15;
    float w = wc[(hh * 16 + k) * 128 + n];
    __nv_bfloat16 h = __float2bfloat16(w);
    __nv_bfloat16 l = __float2bfloat16(w - __bfloat162float(h));
    g_wcimg[hh][0][n * 24 + k] = h;
    g_wcimg[hh][1][n * 24 + k] = l;
}

// =============== fused node kernel (unchanged from Round 4) ===============
#define NB_BIAS 0
#define NB_AH   2048
#define NB_AL   (NB_AH + 34816)
#define NB_W    (NB_AL + 34816)
#define NODE_SMEM (NB_W + 139264)

__global__ void __launch_bounds__(256) node_fused_mma(
    const float* __restrict__ H,
    const float* __restrict__ bq, const float* __restrict__ bk,
    const float* __restrict__ mb1, const float* __restrict__ mb2,
    float* __restrict__ Q, float* __restrict__ K, float* __restrict__ P, int nrows)
{
    extern __shared__ char smem[];
    uint32_t sb = smem_to_u32(smem);
    float* smb = (float*)(smem + NB_BIAS);
    int tid = threadIdx.x, wid = tid >> 5, lane = tid & 31;
    int row0 = blockIdx.x * 128;
    int R = wid * 16;
    int g = lane >> 2, tig = lane & 3;

    if (tid < 128) { smb[tid] = bq[tid]; smb[128 + tid] = bk[tid]; }
    else { int t2 = tid - 128; smb[256 + t2] = mb1[t2]; smb[384 + t2] = mb2[t2]; }

#pragma unroll
    for (int it = 0; it < 16; it++) {
        int idx = it * 256 + tid;
        int r = idx >> 5, c4 = (idx & 31) * 4;
        float4 x = make_float4(0.f, 0.f, 0.f, 0.f);
        if (row0 + r < nrows) x = *(const float4*)(H + (size_t)(row0 + r) * 128 + c4);
        uint32_t h0, l0, h1, l1;
        split2(x.x, x.y, h0, l0);
        split2(x.z, x.w, h1, l1);
        uint32_t o = (uint32_t)(r * 272 + c4 * 2);
        asm volatile("st.shared.v2.b32 [%0], {%1, %2};" :: "r"(sb + NB_AH + o), "r"(h0), "r"(h1));
        asm volatile("st.shared.v2.b32 [%0], {%1, %2};" :: "r"(sb + NB_AL + o), "r"(l0), "r"(l1));
    }
    {
        const uint4* s = (const uint4*)(&g_wimg[0][0][0]);
        uint4* d = (uint4*)(smem + NB_W);
#pragma unroll
        for (int i = 0; i < 34; i++) d[tid + 256 * i] = s[tid + 256 * i];
    }
    __syncthreads();

    uint32_t aH = a_lane_addr(sb + NB_AH, R, lane, 272);
    uint32_t aL = a_lane_addr(sb + NB_AL, R, lane, 272);

    float acc[16][4];
    int rlo = row0 + R + g, rhi = rlo + 8;

    // q
#pragma unroll
    for (int i = 0; i < 16; i++) { acc[i][0] = acc[i][1] = acc[i][2] = acc[i][3] = 0.f; }
    warp_gemm<8>(aH, aL, b_lane_addr(sb + NB_W, lane, 272), b_lane_addr(sb + NB_W + 34816, lane, 272), 272, acc);
#pragma unroll
    for (int nb = 0; nb < 16; nb++) {
        int c = nb * 8 + tig * 2;
        if (rlo < nrows) *(float2*)(Q + (size_t)rlo * 128 + c) = make_float2(acc[nb][0] + smb[c], acc[nb][1] + smb[c + 1]);
        if (rhi < nrows) *(float2*)(Q + (size_t)rhi * 128 + c) = make_float2(acc[nb][2] + smb[c], acc[nb][3] + smb[c + 1]);
    }
    // k
#pragma unroll
    for (int i = 0; i < 16; i++) { acc[i][0] = acc[i][1] = acc[i][2] = acc[i][3] = 0.f; }
    warp_gemm<8>(aH, aL, b_lane_addr(sb + NB_W + 69632, lane, 272), b_lane_addr(sb + NB_W + 104448, lane, 272), 272, acc);
#pragma unroll
    for (int nb = 0; nb < 16; nb++) {
        int c = nb * 8 + tig * 2;
        if (rlo < nrows) *(float2*)(K + (size_t)rlo * 128 + c) = make_float2(acc[nb][0] + smb[128 + c], acc[nb][1] + smb[128 + c + 1]);
        if (rhi < nrows) *(float2*)(K + (size_t)rhi * 128 + c) = make_float2(acc[nb][2] + smb[128 + c], acc[nb][3] + smb[128 + c + 1]);
    }
    __syncthreads();
    {
        const uint4* s = (const uint4*)(&g_wimg[2][0][0]);
        uint4* d = (uint4*)(smem + NB_W);
#pragma unroll
        for (int i = 0; i < 34; i++) d[tid + 256 * i] = s[tid + 256 * i];
    }
    __syncthreads();

    // t1 = silu(h@mw1 + mb1)
#pragma unroll
    for (int i = 0; i < 16; i++) { acc[i][0] = acc[i][1] = acc[i][2] = acc[i][3] = 0.f; }
    warp_gemm<8>(aH, aL, b_lane_addr(sb + NB_W, lane, 272), b_lane_addr(sb + NB_W + 34816, lane, 272), 272, acc);
    __syncthreads();
#pragma unroll
    for (int nb = 0; nb < 16; nb++) {
        int c = nb * 8 + tig * 2;
        uint32_t hi, lo;
        split2(silu_f(acc[nb][0] + smb[256 + c]), silu_f(acc[nb][1] + smb[256 + c + 1]), hi, lo);
        uint32_t o = (uint32_t)((R + g) * 272 + c * 2);
        asm volatile("st.shared.b32 [%0], %1;" :: "r"(sb + NB_AH + o), "r"(hi));
        asm volatile("st.shared.b32 [%0], %1;" :: "r"(sb + NB_AL + o), "r"(lo));
        split2(silu_f(acc[nb][2] + smb[256 + c]), silu_f(acc[nb][3] + smb[256 + c + 1]), hi, lo);
        o = (uint32_t)((R + g + 8) * 272 + c * 2);
        asm volatile("st.shared.b32 [%0], %1;" :: "r"(sb + NB_AH + o), "r"(hi));
        asm volatile("st.shared.b32 [%0], %1;" :: "r"(sb + NB_AL + o), "r"(lo));
    }
    __syncthreads();

    // v = t1@mw2 + mb2
#pragma unroll
    for (int i = 0; i < 16; i++) { acc[i][0] = acc[i][1] = acc[i][2] = acc[i][3] = 0.f; }
    warp_gemm<8>(aH, aL, b_lane_addr(sb + NB_W + 69632, lane, 272), b_lane_addr(sb + NB_W + 104448, lane, 272), 272, acc);
    __syncthreads();
#pragma unroll
    for (int nb = 0; nb < 16; nb++) {
        int c = nb * 8 + tig * 2;
        uint32_t hi, lo;
        split2(acc[nb][0] + smb[384 + c], acc[nb][1] + smb[384 + c + 1], hi, lo);
        uint32_t o = (uint32_t)((R + g) * 272 + c * 2);
        asm volatile("st.shared.b32 [%0], %1;" :: "r"(sb + NB_AH + o), "r"(hi));
        asm volatile("st.shared.b32 [%0], %1;" :: "r"(sb + NB_AL + o), "r"(lo));
        split2(acc[nb][2] + smb[384 + c], acc[nb][3] + smb[384 + c + 1], hi, lo);
        o = (uint32_t)((R + g + 8) * 272 + c * 2);
        asm volatile("st.shared.b32 [%0], %1;" :: "r"(sb + NB_AH + o), "r"(hi));
        asm volatile("st.shared.b32 [%0], %1;" :: "r"(sb + NB_AL + o), "r"(lo));
    }
    {
        const uint4* s = (const uint4*)(&g_wcimg[0][0][0]);
        uint4* d = (uint4*)(smem + NB_W);
#pragma unroll
        for (int i = 0; i < 24; i++) d[tid + 256 * i] = s[tid + 256 * i];
    }
    __syncthreads();

    // P per head
#pragma unroll
    for (int hh = 0; hh < 8; hh++) {
#pragma unroll
        for (int i = 0; i < 16; i++) { acc[i][0] = acc[i][1] = acc[i][2] = acc[i][3] = 0.f; }
        warp_gemm<1>(aH + hh * 32, aL + hh * 32,
                     b_lane_addr(sb + NB_W + hh * 12288, lane, 48),
                     b_lane_addr(sb + NB_W + hh * 12288 + 6144, lane, 48), 48, acc);
#pragma unroll
        for (int nb = 0; nb < 16; nb++) {
            int c = hh * 128 + nb * 8 + tig * 2;
            if (rlo < nrows) *(float2*)(P + (size_t)rlo * 1024 + c) = make_float2(acc[nb][0], acc[nb][1]);
            if (rhi < nrows) *(float2*)(P + (size_t)rhi * 1024 + c) = make_float2(acc[nb][2], acc[nb][3]);
        }
    }
}

// =============== edge logits v2: 74KB smem, re overlays T/W, no atomics ===============
#define EB_BIAS 0
#define EB_TH   512
#define EB_TL   (EB_TH + 18432)
#define EB_WH   (EB_TL + 18432)
#define EB_WL   (EB_WH + 18432)
#define EB_RE   512                    // overlays TH..WL after GEMM (128 x 132 f32 = 67584B)
#define EDGE2_SMEM (EB_WL + 18432)     // 74240

__global__ void __launch_bounds__(256) edge_logits_v2(
    const float* __restrict__ T, const int* __restrict__ EI, const float* __restrict__ BRE)
{
    extern __shared__ char smem[];
    uint32_t sb = smem_to_u32(smem);
    float* smb = (float*)(smem + EB_BIAS);
    float* sRe = (float*)(smem + EB_RE);
    int tid = threadIdx.x, wid = tid >> 5, lane = tid & 31;
    int e0 = blockIdx.x * 128;
    int R = wid * 16;
    int g = lane >> 2, tig = lane & 3;

    if (tid < 128) smb[tid] = BRE[tid];
    {
        const uint4* s = (const uint4*)(&g_wreimg[0][0]);
        uint4* d = (uint4*)(smem + EB_WH);
#pragma unroll
        for (int i = 0; i < 9; i++) d[tid + 256 * i] = s[tid + 256 * i];
    }
#pragma unroll
    for (int it = 0; it < 8; it++) {
        int idx = it * 256 + tid;
        int r = idx >> 4, c4 = (idx & 15) * 4;
        float4 x = *(const float4*)(T + (size_t)(e0 + r) * 64 + c4);
        uint32_t h0, l0, h1, l1;
        split2(x.x, x.y, h0, l0);
        split2(x.z, x.w, h1, l1);
        uint32_t o = (uint32_t)(r * 144 + c4 * 2);
        asm volatile("st.shared.v2.b32 [%0], {%1, %2};" :: "r"(sb + EB_TH + o), "r"(h0), "r"(h1));
        asm volatile("st.shared.v2.b32 [%0], {%1, %2};" :: "r"(sb + EB_TL + o), "r"(l0), "r"(l1));
    }
    __syncthreads();

    float acc[16][4];
#pragma unroll
    for (int i = 0; i < 16; i++) { acc[i][0] = acc[i][1] = acc[i][2] = acc[i][3] = 0.f; }
    warp_gemm<4>(a_lane_addr(sb + EB_TH, R, lane, 144), a_lane_addr(sb + EB_TL, R, lane, 144),
                 b_lane_addr(sb + EB_WH, lane, 144),    b_lane_addr(sb + EB_WL, lane, 144), 144, acc);
    __syncthreads();   // all warps done reading T/W -> safe to overlay with re

#pragma unroll
    for (int nb = 0; nb < 16; nb++) {
        int c = nb * 8 + tig * 2;
        float b0 = smb[c], b1 = smb[c + 1];
        *(float2*)(sRe + (R + g) * 132 + c)     = make_float2(silu_f(acc[nb][0] + b0), silu_f(acc[nb][1] + b1));
        *(float2*)(sRe + (R + g + 8) * 132 + c) = make_float2(silu_f(acc[nb][2] + b0), silu_f(acc[nb][3] + b1));
    }
    __syncthreads();

    // gather phase: 16 edges per warp, write raw logits (no atomics)
#pragma unroll
    for (int i = 0; i < 16; i++) {
        int el = wid * 16 + i;
        int e = e0 + el;
        int nj = EI[e];
        int ni = EI[NE + e];
        float4 q4 = *(const float4*)(g_q + (size_t)ni * 128 + lane * 4);
        float4 k4 = *(const float4*)(g_k + (size_t)nj * 128 + lane * 4);
        float4 r4 = *(const float4*)(sRe + el * 132 + lane * 4);
        float p = q4.x * k4.x * r4.x + q4.y * k4.y * r4.y
                + q4.z * k4.z * r4.z + q4.w * k4.w * r4.w;
        p += __shfl_xor_sync(0xffffffffu, p, 1);
        p += __shfl_xor_sync(0xffffffffu, p, 2);
        if ((lane & 3) == 0) g_a[(size_t)e * 8 + (lane >> 2)] = p;
    }
}

// =============== CSR bookkeeping ===============
__global__ void init_kernel() {
    int i = blockIdx.x * blockDim.x + threadIdx.x;
    if (i < NN) { g_cnt[i] = 0; g_cntI[i] = 0; }
}
__global__ void hist_kernel(const int* __restrict__ EI) {
    int e = blockIdx.x * blockDim.x + threadIdx.x;
    if (e < NE) {
        atomicAdd(&g_cnt[EI[e]], 1);
        atomicAdd(&g_cntI[EI[NE + e]], 1);
    }
}
__global__ void __launch_bounds__(1024) scan_kernel(int which) {
    int* cnt = which ? g_cntI : g_cnt;
    int* off = which ? g_offI : g_off;
    __shared__ int ssum[1024];
    int tid = threadIdx.x;
    const int CH = (NN + 1023) / 1024;
    int lo = tid * CH;
    int hi = lo + CH; if (hi > NN) hi = NN; if (lo > NN) lo = NN;
    int s = 0;
    for (int i = lo; i < hi; i++) s += cnt[i];
    ssum[tid] = s;
    __syncthreads();
    for (int o = 1; o < 1024; o <<= 1) {
        int v = (tid >= o) ? ssum[tid - o] : 0;
        __syncthreads();
        ssum[tid] += v;
        __syncthreads();
    }
    int run = ssum[tid] - s;
    for (int i = lo; i < hi; i++) {
        int c = cnt[i];
        off[i] = run;
        cnt[i] = run;
        run += c;
    }
    if (tid == 1023) off[NN] = ssum[1023];
}
__global__ void scatter_kernel(const int* __restrict__ EI) {
    int e = blockIdx.x * blockDim.x + threadIdx.x;
    if (e < NE) {
        int pj = atomicAdd(&g_cnt[EI[e]], 1);
        g_order[pj] = e;
        int pi = atomicAdd(&g_cntI[EI[NE + e]], 1);
        g_orderI[pi] = e;
    }
}

// =============== segment softmax: warp per destination node, register-resident ===============
__global__ void __launch_bounds__(256) segment_softmax() {
    int i = blockIdx.x * 8 + (threadIdx.x >> 5);
    int lane = threadIdx.x & 31;
    if (i >= NN) return;
    int s = g_offI[i];
    int d = g_offI[i + 1] - s;
    if (d == 0) return;
    int nv = d * 8;
    int iters = (nv + 31) >> 5;
    const int CAP = 8;
    float vals[CAP];

    float mx = -1e30f;
#pragma unroll
    for (int it = 0; it < CAP; it++) {
        if (it < iters) {
            int v = it * 32 + lane;
            float val = -1e30f;
            if (v < nv) val = g_a[(size_t)g_orderI[s + (v >> 3)] * 8 + (v & 7)];
            vals[it] = val;
            mx = fmaxf(mx, val);
        }
    }
    for (int it = CAP; it < iters; it++) {
        int v = it * 32 + lane;
        if (v < nv) mx = fmaxf(mx, g_a[(size_t)g_orderI[s + (v >> 3)] * 8 + (v & 7)]);
    }
    mx = fmaxf(mx, __shfl_xor_sync(0xffffffffu, mx, 16));
    mx = fmaxf(mx, __shfl_xor_sync(0xffffffffu, mx, 8));

    float sum = 0.f;
#pragma unroll
    for (int it = 0; it < CAP; it++) {
        if (it < iters) {
            int v = it * 32 + lane;
            float ex = 0.f;
            if (v < nv) ex = __expf(vals[it] - mx);
            vals[it] = ex;
            sum += ex;
        }
    }
    for (int it = CAP; it < iters; it++) {
        int v = it * 32 + lane;
        if (v < nv) sum += __expf(g_a[(size_t)g_orderI[s + (v >> 3)] * 8 + (v & 7)] - mx);
    }
    sum += __shfl_xor_sync(0xffffffffu, sum, 16);
    sum += __shfl_xor_sync(0xffffffffu, sum, 8);

    float scale = sqrtf((float)d) * 0.25f / sum;
#pragma unroll
    for (int it = 0; it < CAP; it++) {
        if (it < iters) {
            int v = it * 32 + lane;
            if (v < nv) g_a[(size_t)g_orderI[s + (v >> 3)] * 8 + (v & 7)] = vals[it] * scale;
        }
    }
    for (int it = CAP; it < iters; it++) {
        int v = it * 32 + lane;
        if (v < nv) {
            size_t idx = (size_t)g_orderI[s + (v >> 3)] * 8 + (v & 7);
            g_a[idx] = __expf(g_a[idx] - mx) * scale;
        }
    }
}

// =============== output: warp per source node (CSR by n_j) ===============
__global__ void __launch_bounds__(256) edge_out_sorted(
    const float* __restrict__ BC, float* __restrict__ OUT)
{
    int j = blockIdx.x * 8 + (threadIdx.x >> 5);
    int lane = threadIdx.x & 31;
    if (j >= NN) return;
    int s = g_off[j], e_end = g_off[j + 1];
    if (s == e_end) return;

    const float* Pj = g_P + (size_t)j * 1024;
    float4 p[8];
#pragma unroll
    for (int h = 0; h < 8; h++)
        p[h] = *(const float4*)(Pj + h * 128 + lane * 4);
    float4 b4 = *(const float4*)(BC + lane * 4);

    for (int x = s; x < e_end; x++) {
        int e = g_order[x];
        float w = 0.f;
        if (lane < 8) w = g_a[(size_t)e * 8 + lane];

        float4 acc = b4;
#pragma unroll
        for (int h = 0; h < 8; h++) {
            float wh = __shfl_sync(0xffffffffu, w, h);
            acc.x = fmaf(wh, p[h].x, acc.x);
            acc.y = fmaf(wh, p[h].y, acc.y);
            acc.z = fmaf(wh, p[h].z, acc.z);
            acc.w = fmaf(wh, p[h].w, acc.w);
        }
        *(float4*)(OUT + (size_t)e * 128 + lane * 4) = acc;
    }
}

// =============== launch ===============
extern "C" void kernel_launch(void* const* d_in, const int* in_sizes, int n_in,
                              void* d_out, int out_size)
{
    const float* h   = (const float*)d_in[0];
    const float* t   = (const float*)d_in[1];
    const int*   ei  = (const int*)  d_in[2];
    const float* wq  = (const float*)d_in[3];
    const float* bq  = (const float*)d_in[4];
    const float* wk  = (const float*)d_in[5];
    const float* bk  = (const float*)d_in[6];
    const float* wre = (const float*)d_in[7];
    const float* bre = (const float*)d_in[8];
    const float* mw1 = (const float*)d_in[9];
    const float* mb1 = (const float*)d_in[10];
    const float* mw2 = (const float*)d_in[11];
    const float* mb2 = (const float*)d_in[12];
    const float* wc  = (const float*)d_in[13];
    const float* bc  = (const float*)d_in[14];
    float* out = (float*)d_out;

    (void)in_sizes; (void)n_in; (void)out_size;

    cudaFuncSetAttribute(node_fused_mma, cudaFuncAttributeMaxDynamicSharedMemorySize, NODE_SMEM);
    cudaFuncSetAttribute(edge_logits_v2, cudaFuncAttributeMaxDynamicSharedMemorySize, EDGE2_SMEM);

    float *q_p, *k_p, *P_p;
    cudaGetSymbolAddress((void**)&q_p, g_q);
    cudaGetSymbolAddress((void**)&k_p, g_k);
    cudaGetSymbolAddress((void**)&P_p, g_P);

    init_kernel<<<(NN + 255) / 256, 256>>>();
    hist_kernel<<<(NE + 255) / 256, 256>>>(ei);
    scan_kernel<<<1, 1024>>>(0);
    scan_kernel<<<1, 1024>>>(1);
    scatter_kernel<<<(NE + 255) / 256, 256>>>(ei);

    prep_w128<<<256, 256>>>(wq, wk, mw1, mw2);
    prep_wre<<<32, 256>>>(wre);
    prep_wc<<<64, 256>>>(wc);

    node_fused_mma<<<(NN + 127) / 128, 256, NODE_SMEM>>>(h, bq, bk, mb1, mb2, q_p, k_p, P_p, NN);

    edge_logits_v2<<<NE / 128, 256, EDGE2_SMEM>>>(t, ei, bre);
    segment_softmax<<<(NN + 7) / 8, 256>>>();
    edge_out_sorted<<<(NN + 7) / 8, 256>>>(bc, out);
}

// round 6
// speedup vs baseline: 1.6216x; 1.2933x over previous
#include <cuda_runtime.h>
#include <cuda_bf16.h>
#include <math.h>
#include <cstdint>

#define NN 50000
#define NE 400000

// =============== mma.sync helpers ===============
__device__ __forceinline__ uint32_t smem_to_u32(const void* p) {
    uint32_t a;
    asm("{ .reg .u64 t; cvta.to.shared.u64 t, %1; cvt.u32.u64 %0, t; }" : "=r"(a) : "l"(p));
    return a;
}
__device__ __forceinline__ void ldsm_x4(uint32_t addr, uint32_t* r) {
    asm volatile("ldmatrix.sync.aligned.m8n8.x4.shared.b16 {%0,%1,%2,%3}, [%4];"
        : "=r"(r[0]), "=r"(r[1]), "=r"(r[2]), "=r"(r[3]) : "r"(addr));
}
__device__ __forceinline__ void mma_bf16(float* d, const uint32_t* a, const uint32_t* b) {
    asm volatile("mma.sync.aligned.m16n8k16.row.col.f32.bf16.bf16.f32 "
        "{%0,%1,%2,%3}, {%4,%5,%6,%7}, {%8,%9}, {%0,%1,%2,%3};"
        : "+f"(d[0]), "+f"(d[1]), "+f"(d[2]), "+f"(d[3])
        : "r"(a[0]), "r"(a[1]), "r"(a[2]), "r"(a[3]), "r"(b[0]), "r"(b[1]));
}
__device__ __forceinline__ uint32_t a_lane_addr(uint32_t base, int R, int lane, int stride) {
    int t = lane >> 3;
    int row = R + (lane & 7) + (t & 1) * 8;
    int k8  = (t >> 1) * 8;
    return base + row * stride + k8 * 2;
}
__device__ __forceinline__ uint32_t b_lane_addr(uint32_t base, int lane, int stride) {
    int t = lane >> 3;
    int n  = (lane & 7) + (t >> 1) * 8;
    int k8 = (t & 1) * 8;
    return base + n * stride + k8 * 2;
}
template<int KSTEPS>
__device__ __forceinline__ void warp_gemm(
    uint32_t aH, uint32_t aL, uint32_t bH, uint32_t bL, int bstride, float (*acc)[4])
{
#pragma unroll
    for (int ks = 0; ks < KSTEPS; ks++) {
        uint32_t rah[4], ral[4];
        ldsm_x4(aH + ks * 32, rah);
        ldsm_x4(aL + ks * 32, ral);
#pragma unroll
        for (int nbp = 0; nbp < 8; nbp++) {
            uint32_t bh[4], bl[4];
            ldsm_x4(bH + nbp * 16 * bstride + ks * 32, bh);
            ldsm_x4(bL + nbp * 16 * bstride + ks * 32, bl);
            mma_bf16(acc[2 * nbp],     rah, bh);
            mma_bf16(acc[2 * nbp],     rah, bl);
            mma_bf16(acc[2 * nbp],     ral, bh);
            mma_bf16(acc[2 * nbp + 1], rah, bh + 2);
            mma_bf16(acc[2 * nbp + 1], rah, bl + 2);
            mma_bf16(acc[2 * nbp + 1], ral, bh + 2);
        }
    }
}

__device__ __forceinline__ float silu_f(float x) { return x / (1.0f + __expf(-x)); }
__device__ __forceinline__ void split2(float x0, float x1, uint32_t& hi, uint32_t& lo) {
    __nv_bfloat16 h0 = __float2bfloat16(x0), h1 = __float2bfloat16(x1);
    __nv_bfloat16 l0 = __float2bfloat16(x0 - __bfloat162float(h0));
    __nv_bfloat16 l1 = __float2bfloat16(x1 - __bfloat162float(h1));
    __nv_bfloat162 H; H.x = h0; H.y = h1;
    __nv_bfloat162 L; L.x = l0; L.y = l1;
    hi = *(uint32_t*)&H; lo = *(uint32_t*)&L;
}

// =============== scratch globals ===============
__device__ __align__(16) float g_q [NN * 128];
__device__ __align__(16) float g_k [NN * 128];
__device__ __align__(16) float g_P [(size_t)NN * 1024];
__device__ __align__(16) float g_a [(size_t)NE * 8];
__device__ int g_cnt  [NN];
__device__ int g_cntI [NN];
__device__ int g_off  [NN + 1];
__device__ int g_offI [NN + 1];
__device__ int g_order [NE];
__device__ int g_orderI[NE];
#define SCH 512
#define SNB ((NN + SCH - 1) / SCH)    // 98
__device__ int g_part[2][SNB];
__device__ int g_pp  [2][SNB];
__device__ __align__(16) __nv_bfloat16 g_wimg [4][2][128 * 136];
__device__ __align__(16) __nv_bfloat16 g_wreimg[2][128 * 72];
__device__ __align__(16) __nv_bfloat16 g_wcimg [8][2][128 * 24];

// =============== weight prep ===============
__global__ void prep_w128(const float* __restrict__ wq, const float* __restrict__ wk,
                          const float* __restrict__ mw1, const float* __restrict__ mw2) {
    int gid = blockIdx.x * blockDim.x + threadIdx.x;
    int m = gid >> 14, idx = gid & 16383;
    const float* W = (m == 0) ? wq : (m == 1) ? wk : (m == 2) ? mw1 : mw2;
    int k = idx >> 7, n = idx & 127;
    float w = W[k * 128 + n];
    __nv_bfloat16 h = __float2bfloat16(w);
    __nv_bfloat16 l = __float2bfloat16(w - __bfloat162float(h));
    g_wimg[m][0][n * 136 + k] = h;
    g_wimg[m][1][n * 136 + k] = l;
}
__global__ void prep_wre(const float* __restrict__ wre) {
    int idx = blockIdx.x * blockDim.x + threadIdx.x;
    int k = idx >> 7, n = idx & 127;
    float w = wre[k * 128 + n];
    __nv_bfloat16 h = __float2bfloat16(w);
    __nv_bfloat16 l = __float2bfloat16(w - __bfloat162float(h));
    g_wreimg[0][n * 72 + k] = h;
    g_wreimg[1][n * 72 + k] = l;
}
__global__ void prep_wc(const float* __restrict__ wc) {
    int gid = blockIdx.x * blockDim.x + threadIdx.x;
    int hh = gid >> 11, idx = gid & 2047;
    int n = idx >> 4, k = idx & 15;
    float w = wc[(hh * 16 + k) * 128 + n];
    __nv_bfloat16 h = __float2bfloat16(w);
    __nv_bfloat16 l = __float2bfloat16(w - __bfloat162float(h));
    g_wcimg[hh][0][n * 24 + k] = h;
    g_wcimg[hh][1][n * 24 + k] = l;
}

// =============== fused node kernel ===============
#define NB_BIAS 0
#define NB_AH   2048
#define NB_AL   (NB_AH + 34816)
#define NB_W    (NB_AL + 34816)
#define NODE_SMEM (NB_W + 139264)

__global__ void __launch_bounds__(256) node_fused_mma(
    const float* __restrict__ H,
    const float* __restrict__ bq, const float* __restrict__ bk,
    const float* __restrict__ mb1, const float* __restrict__ mb2,
    float* __restrict__ Q, float* __restrict__ K, float* __restrict__ P, int nrows)
{
    extern __shared__ char smem[];
    uint32_t sb = smem_to_u32(smem);
    float* smb = (float*)(smem + NB_BIAS);
    int tid = threadIdx.x, wid = tid >> 5, lane = tid & 31;
    int row0 = blockIdx.x * 128;
    int R = wid * 16;
    int g = lane >> 2, tig = lane & 3;

    if (tid < 128) { smb[tid] = bq[tid]; smb[128 + tid] = bk[tid]; }
    else { int t2 = tid - 128; smb[256 + t2] = mb1[t2]; smb[384 + t2] = mb2[t2]; }

#pragma unroll
    for (int it = 0; it < 16; it++) {
        int idx = it * 256 + tid;
        int r = idx >> 5, c4 = (idx & 31) * 4;
        float4 x = make_float4(0.f, 0.f, 0.f, 0.f);
        if (row0 + r < nrows) x = *(const float4*)(H + (size_t)(row0 + r) * 128 + c4);
        uint32_t h0, l0, h1, l1;
        split2(x.x, x.y, h0, l0);
        split2(x.z, x.w, h1, l1);
        uint32_t o = (uint32_t)(r * 272 + c4 * 2);
        asm volatile("st.shared.v2.b32 [%0], {%1, %2};" :: "r"(sb + NB_AH + o), "r"(h0), "r"(h1));
        asm volatile("st.shared.v2.b32 [%0], {%1, %2};" :: "r"(sb + NB_AL + o), "r"(l0), "r"(l1));
    }
    {
        const uint4* s = (const uint4*)(&g_wimg[0][0][0]);
        uint4* d = (uint4*)(smem + NB_W);
#pragma unroll
        for (int i = 0; i < 34; i++) d[tid + 256 * i] = s[tid + 256 * i];
    }
    __syncthreads();

    uint32_t aH = a_lane_addr(sb + NB_AH, R, lane, 272);
    uint32_t aL = a_lane_addr(sb + NB_AL, R, lane, 272);

    float acc[16][4];
    int rlo = row0 + R + g, rhi = rlo + 8;

    // q
#pragma unroll
    for (int i = 0; i < 16; i++) { acc[i][0] = acc[i][1] = acc[i][2] = acc[i][3] = 0.f; }
    warp_gemm<8>(aH, aL, b_lane_addr(sb + NB_W, lane, 272), b_lane_addr(sb + NB_W + 34816, lane, 272), 272, acc);
#pragma unroll
    for (int nb = 0; nb < 16; nb++) {
        int c = nb * 8 + tig * 2;
        if (rlo < nrows) *(float2*)(Q + (size_t)rlo * 128 + c) = make_float2(acc[nb][0] + smb[c], acc[nb][1] + smb[c + 1]);
        if (rhi < nrows) *(float2*)(Q + (size_t)rhi * 128 + c) = make_float2(acc[nb][2] + smb[c], acc[nb][3] + smb[c + 1]);
    }
    // k
#pragma unroll
    for (int i = 0; i < 16; i++) { acc[i][0] = acc[i][1] = acc[i][2] = acc[i][3] = 0.f; }
    warp_gemm<8>(aH, aL, b_lane_addr(sb + NB_W + 69632, lane, 272), b_lane_addr(sb + NB_W + 104448, lane, 272), 272, acc);
#pragma unroll
    for (int nb = 0; nb < 16; nb++) {
        int c = nb * 8 + tig * 2;
        if (rlo < nrows) *(float2*)(K + (size_t)rlo * 128 + c) = make_float2(acc[nb][0] + smb[128 + c], acc[nb][1] + smb[128 + c + 1]);
        if (rhi < nrows) *(float2*)(K + (size_t)rhi * 128 + c) = make_float2(acc[nb][2] + smb[128 + c], acc[nb][3] + smb[128 + c + 1]);
    }
    __syncthreads();
    {
        const uint4* s = (const uint4*)(&g_wimg[2][0][0]);
        uint4* d = (uint4*)(smem + NB_W);
#pragma unroll
        for (int i = 0; i < 34; i++) d[tid + 256 * i] = s[tid + 256 * i];
    }
    __syncthreads();

    // t1 = silu(h@mw1 + mb1)
#pragma unroll
    for (int i = 0; i < 16; i++) { acc[i][0] = acc[i][1] = acc[i][2] = acc[i][3] = 0.f; }
    warp_gemm<8>(aH, aL, b_lane_addr(sb + NB_W, lane, 272), b_lane_addr(sb + NB_W + 34816, lane, 272), 272, acc);
    __syncthreads();
#pragma unroll
    for (int nb = 0; nb < 16; nb++) {
        int c = nb * 8 + tig * 2;
        uint32_t hi, lo;
        split2(silu_f(acc[nb][0] + smb[256 + c]), silu_f(acc[nb][1] + smb[256 + c + 1]), hi, lo);
        uint32_t o = (uint32_t)((R + g) * 272 + c * 2);
        asm volatile("st.shared.b32 [%0], %1;" :: "r"(sb + NB_AH + o), "r"(hi));
        asm volatile("st.shared.b32 [%0], %1;" :: "r"(sb + NB_AL + o), "r"(lo));
        split2(silu_f(acc[nb][2] + smb[256 + c]), silu_f(acc[nb][3] + smb[256 + c + 1]), hi, lo);
        o = (uint32_t)((R + g + 8) * 272 + c * 2);
        asm volatile("st.shared.b32 [%0], %1;" :: "r"(sb + NB_AH + o), "r"(hi));
        asm volatile("st.shared.b32 [%0], %1;" :: "r"(sb + NB_AL + o), "r"(lo));
    }
    __syncthreads();

    // v = t1@mw2 + mb2
#pragma unroll
    for (int i = 0; i < 16; i++) { acc[i][0] = acc[i][1] = acc[i][2] = acc[i][3] = 0.f; }
    warp_gemm<8>(aH, aL, b_lane_addr(sb + NB_W + 69632, lane, 272), b_lane_addr(sb + NB_W + 104448, lane, 272), 272, acc);
    __syncthreads();
#pragma unroll
    for (int nb = 0; nb < 16; nb++) {
        int c = nb * 8 + tig * 2;
        uint32_t hi, lo;
        split2(acc[nb][0] + smb[384 + c], acc[nb][1] + smb[384 + c + 1], hi, lo);
        uint32_t o = (uint32_t)((R + g) * 272 + c * 2);
        asm volatile("st.shared.b32 [%0], %1;" :: "r"(sb + NB_AH + o), "r"(hi));
        asm volatile("st.shared.b32 [%0], %1;" :: "r"(sb + NB_AL + o), "r"(lo));
        split2(acc[nb][2] + smb[384 + c], acc[nb][3] + smb[384 + c + 1], hi, lo);
        o = (uint32_t)((R + g + 8) * 272 + c * 2);
        asm volatile("st.shared.b32 [%0], %1;" :: "r"(sb + NB_AH + o), "r"(hi));
        asm volatile("st.shared.b32 [%0], %1;" :: "r"(sb + NB_AL + o), "r"(lo));
    }
    {
        const uint4* s = (const uint4*)(&g_wcimg[0][0][0]);
        uint4* d = (uint4*)(smem + NB_W);
#pragma unroll
        for (int i = 0; i < 24; i++) d[tid + 256 * i] = s[tid + 256 * i];
    }
    __syncthreads();

    // P per head
#pragma unroll
    for (int hh = 0; hh < 8; hh++) {
#pragma unroll
        for (int i = 0; i < 16; i++) { acc[i][0] = acc[i][1] = acc[i][2] = acc[i][3] = 0.f; }
        warp_gemm<1>(aH + hh * 32, aL + hh * 32,
                     b_lane_addr(sb + NB_W + hh * 12288, lane, 48),
                     b_lane_addr(sb + NB_W + hh * 12288 + 6144, lane, 48), 48, acc);
#pragma unroll
        for (int nb = 0; nb < 16; nb++) {
            int c = hh * 128 + nb * 8 + tig * 2;
            if (rlo < nrows) *(float2*)(P + (size_t)rlo * 1024 + c) = make_float2(acc[nb][0], acc[nb][1]);
            if (rhi < nrows) *(float2*)(P + (size_t)rhi * 1024 + c) = make_float2(acc[nb][2], acc[nb][3]);
        }
    }
}

// =============== edge logits v2 ===============
#define EB_BIAS 0
#define EB_TH   512
#define EB_TL   (EB_TH + 18432)
#define EB_WH   (EB_TL + 18432)
#define EB_WL   (EB_WH + 18432)
#define EB_RE   512
#define EDGE2_SMEM (EB_WL + 18432)

__global__ void __launch_bounds__(256) edge_logits_v2(
    const float* __restrict__ T, const int* __restrict__ EI, const float* __restrict__ BRE)
{
    extern __shared__ char smem[];
    uint32_t sb = smem_to_u32(smem);
    float* smb = (float*)(smem + EB_BIAS);
    float* sRe = (float*)(smem + EB_RE);
    int tid = threadIdx.x, wid = tid >> 5, lane = tid & 31;
    int e0 = blockIdx.x * 128;
    int R = wid * 16;
    int g = lane >> 2, tig = lane & 3;

    if (tid < 128) smb[tid] = BRE[tid];
    {
        const uint4* s = (const uint4*)(&g_wreimg[0][0]);
        uint4* d = (uint4*)(smem + EB_WH);
#pragma unroll
        for (int i = 0; i < 9; i++) d[tid + 256 * i] = s[tid + 256 * i];
    }
#pragma unroll
    for (int it = 0; it < 8; it++) {
        int idx = it * 256 + tid;
        int r = idx >> 4, c4 = (idx & 15) * 4;
        float4 x = *(const float4*)(T + (size_t)(e0 + r) * 64 + c4);
        uint32_t h0, l0, h1, l1;
        split2(x.x, x.y, h0, l0);
        split2(x.z, x.w, h1, l1);
        uint32_t o = (uint32_t)(r * 144 + c4 * 2);
        asm volatile("st.shared.v2.b32 [%0], {%1, %2};" :: "r"(sb + EB_TH + o), "r"(h0), "r"(h1));
        asm volatile("st.shared.v2.b32 [%0], {%1, %2};" :: "r"(sb + EB_TL + o), "r"(l0), "r"(l1));
    }
    __syncthreads();

    float acc[16][4];
#pragma unroll
    for (int i = 0; i < 16; i++) { acc[i][0] = acc[i][1] = acc[i][2] = acc[i][3] = 0.f; }
    warp_gemm<4>(a_lane_addr(sb + EB_TH, R, lane, 144), a_lane_addr(sb + EB_TL, R, lane, 144),
                 b_lane_addr(sb + EB_WH, lane, 144),    b_lane_addr(sb + EB_WL, lane, 144), 144, acc);
    __syncthreads();

#pragma unroll
    for (int nb = 0; nb < 16; nb++) {
        int c = nb * 8 + tig * 2;
        float b0 = smb[c], b1 = smb[c + 1];
        *(float2*)(sRe + (R + g) * 132 + c)     = make_float2(silu_f(acc[nb][0] + b0), silu_f(acc[nb][1] + b1));
        *(float2*)(sRe + (R + g + 8) * 132 + c) = make_float2(silu_f(acc[nb][2] + b0), silu_f(acc[nb][3] + b1));
    }
    __syncthreads();

#pragma unroll
    for (int i = 0; i < 16; i++) {
        int el = wid * 16 + i;
        int e = e0 + el;
        int nj = EI[e];
        int ni = EI[NE + e];
        float4 q4 = *(const float4*)(g_q + (size_t)ni * 128 + lane * 4);
        float4 k4 = *(const float4*)(g_k + (size_t)nj * 128 + lane * 4);
        float4 r4 = *(const float4*)(sRe + el * 132 + lane * 4);
        float p = q4.x * k4.x * r4.x + q4.y * k4.y * r4.y
                + q4.z * k4.z * r4.z + q4.w * k4.w * r4.w;
        p += __shfl_xor_sync(0xffffffffu, p, 1);
        p += __shfl_xor_sync(0xffffffffu, p, 2);
        if ((lane & 3) == 0) g_a[(size_t)e * 8 + (lane >> 2)] = p;
    }
}

// =============== CSR: hist + 3-phase chip-wide scan + scatter ===============
__global__ void init_kernel() {
    int i = blockIdx.x * blockDim.x + threadIdx.x;
    if (i < NN) { g_cnt[i] = 0; g_cntI[i] = 0; }
}
__global__ void hist_kernel(const int* __restrict__ EI) {
    int e = blockIdx.x * blockDim.x + threadIdx.x;
    if (e < NE) {
        atomicAdd(&g_cnt[EI[e]], 1);
        atomicAdd(&g_cntI[EI[NE + e]], 1);
    }
}
// Phase A: per-chunk sums for both arrays
__global__ void __launch_bounds__(SCH) scanA() {
    const int* cnt = blockIdx.y ? g_cntI : g_cnt;
    __shared__ int sm[SCH];
    int tid = threadIdx.x;
    int i = blockIdx.x * SCH + tid;
    sm[tid] = (i < NN) ? cnt[i] : 0;
    __syncthreads();
#pragma unroll
    for (int off = SCH / 2; off > 0; off >>= 1) {
        if (tid < off) sm[tid] += sm[tid + off];
        __syncthreads();
    }
    if (tid == 0) g_part[blockIdx.y][blockIdx.x] = sm[0];
}
// Phase B: scan the partials (both arrays in one tiny block)
__global__ void __launch_bounds__(256) scanB() {
    __shared__ int sm[2][128];
    int tid = threadIdx.x;
    int y = tid >> 7, x = tid & 127;
    sm[y][x] = (x < SNB) ? g_part[y][x] : 0;
    __syncthreads();
#pragma unroll
    for (int off = 1; off < 128; off <<= 1) {
        int v = (x >= off) ? sm[y][x - off] : 0;
        __syncthreads();
        sm[y][x] += v;
        __syncthreads();
    }
    if (x < SNB) g_pp[y][x] = sm[y][x] - g_part[y][x];   // exclusive
    if (x == SNB - 1) {
        if (y == 0) g_off[NN]  = sm[0][x];
        else        g_offI[NN] = sm[1][x];
    }
}
// Phase C: in-chunk exclusive scan + base; emit offsets and cursors
__global__ void __launch_bounds__(SCH) scanC() {
    int* cnt = blockIdx.y ? g_cntI : g_cnt;
    int* off = blockIdx.y ? g_offI : g_off;
    __shared__ int sm[SCH];
    int tid = threadIdx.x;
    int i = blockIdx.x * SCH + tid;
    int self = (i < NN) ? cnt[i] : 0;
    sm[tid] = self;
    __syncthreads();
#pragma unroll
    for (int o = 1; o < SCH; o <<= 1) {
        int v = (tid >= o) ? sm[tid - o] : 0;
        __syncthreads();
        sm[tid] += v;
        __syncthreads();
    }
    if (i < NN) {
        int pref = g_pp[blockIdx.y][blockIdx.x] + sm[tid] - self;
        off[i] = pref;
        cnt[i] = pref;   // cursor for scatter
    }
}
__global__ void scatter_kernel(const int* __restrict__ EI) {
    int e = blockIdx.x * blockDim.x + threadIdx.x;
    if (e < NE) {
        int pj = atomicAdd(&g_cnt[EI[e]], 1);
        g_order[pj] = e;
        int pi = atomicAdd(&g_cntI[EI[NE + e]], 1);
        g_orderI[pi] = e;
    }
}

// =============== segment softmax ===============
__global__ void __launch_bounds__(256) segment_softmax() {
    int i = blockIdx.x * 8 + (threadIdx.x >> 5);
    int lane = threadIdx.x & 31;
    if (i >= NN) return;
    int s = g_offI[i];
    int d = g_offI[i + 1] - s;
    if (d == 0) return;
    int nv = d * 8;
    int iters = (nv + 31) >> 5;
    const int CAP = 8;
    float vals[CAP];

    float mx = -1e30f;
#pragma unroll
    for (int it = 0; it < CAP; it++) {
        if (it < iters) {
            int v = it * 32 + lane;
            float val = -1e30f;
            if (v < nv) val = g_a[(size_t)g_orderI[s + (v >> 3)] * 8 + (v & 7)];
            vals[it] = val;
            mx = fmaxf(mx, val);
        }
    }
    for (int it = CAP; it < iters; it++) {
        int v = it * 32 + lane;
        if (v < nv) mx = fmaxf(mx, g_a[(size_t)g_orderI[s + (v >> 3)] * 8 + (v & 7)]);
    }
    mx = fmaxf(mx, __shfl_xor_sync(0xffffffffu, mx, 16));
    mx = fmaxf(mx, __shfl_xor_sync(0xffffffffu, mx, 8));

    float sum = 0.f;
#pragma unroll
    for (int it = 0; it < CAP; it++) {
        if (it < iters) {
            int v = it * 32 + lane;
            float ex = 0.f;
            if (v < nv) ex = __expf(vals[it] - mx);
            vals[it] = ex;
            sum += ex;
        }
    }
    for (int it = CAP; it < iters; it++) {
        int v = it * 32 + lane;
        if (v < nv) sum += __expf(g_a[(size_t)g_orderI[s + (v >> 3)] * 8 + (v & 7)] - mx);
    }
    sum += __shfl_xor_sync(0xffffffffu, sum, 16);
    sum += __shfl_xor_sync(0xffffffffu, sum, 8);

    float scale = sqrtf((float)d) * 0.25f / sum;
#pragma unroll
    for (int it = 0; it < CAP; it++) {
        if (it < iters) {
            int v = it * 32 + lane;
            if (v < nv) g_a[(size_t)g_orderI[s + (v >> 3)] * 8 + (v & 7)] = vals[it] * scale;
        }
    }
    for (int it = CAP; it < iters; it++) {
        int v = it * 32 + lane;
        if (v < nv) {
            size_t idx = (size_t)g_orderI[s + (v >> 3)] * 8 + (v & 7);
            g_a[idx] = __expf(g_a[idx] - mx) * scale;
        }
    }
}

// =============== output ===============
__global__ void __launch_bounds__(256) edge_out_sorted(
    const float* __restrict__ BC, float* __restrict__ OUT)
{
    int j = blockIdx.x * 8 + (threadIdx.x >> 5);
    int lane = threadIdx.x & 31;
    if (j >= NN) return;
    int s = g_off[j], e_end = g_off[j + 1];
    if (s == e_end) return;

    const float* Pj = g_P + (size_t)j * 1024;
    float4 p[8];
#pragma unroll
    for (int h = 0; h < 8; h++)
        p[h] = *(const float4*)(Pj + h * 128 + lane * 4);
    float4 b4 = *(const float4*)(BC + lane * 4);

    for (int x = s; x < e_end; x++) {
        int e = g_order[x];
        float w = 0.f;
        if (lane < 8) w = g_a[(size_t)e * 8 + lane];

        float4 acc = b4;
#pragma unroll
        for (int h = 0; h < 8; h++) {
            float wh = __shfl_sync(0xffffffffu, w, h);
            acc.x = fmaf(wh, p[h].x, acc.x);
            acc.y = fmaf(wh, p[h].y, acc.y);
            acc.z = fmaf(wh, p[h].z, acc.z);
            acc.w = fmaf(wh, p[h].w, acc.w);
        }
        *(float4*)(OUT + (size_t)e * 128 + lane * 4) = acc;
    }
}

// =============== launch ===============
extern "C" void kernel_launch(void* const* d_in, const int* in_sizes, int n_in,
                              void* d_out, int out_size)
{
    const float* h   = (const float*)d_in[0];
    const float* t   = (const float*)d_in[1];
    const int*   ei  = (const int*)  d_in[2];
    const float* wq  = (const float*)d_in[3];
    const float* bq  = (const float*)d_in[4];
    const float* wk  = (const float*)d_in[5];
    const float* bk  = (const float*)d_in[6];
    const float* wre = (const float*)d_in[7];
    const float* bre = (const float*)d_in[8];
    const float* mw1 = (const float*)d_in[9];
    const float* mb1 = (const float*)d_in[10];
    const float* mw2 = (const float*)d_in[11];
    const float* mb2 = (const float*)d_in[12];
    const float* wc  = (const float*)d_in[13];
    const float* bc  = (const float*)d_in[14];
    float* out = (float*)d_out;

    (void)in_sizes; (void)n_in; (void)out_size;

    cudaFuncSetAttribute(node_fused_mma, cudaFuncAttributeMaxDynamicSharedMemorySize, NODE_SMEM);
    cudaFuncSetAttribute(edge_logits_v2, cudaFuncAttributeMaxDynamicSharedMemorySize, EDGE2_SMEM);

    float *q_p, *k_p, *P_p;
    cudaGetSymbolAddress((void**)&q_p, g_q);
    cudaGetSymbolAddress((void**)&k_p, g_k);
    cudaGetSymbolAddress((void**)&P_p, g_P);

    init_kernel<<<(NN + 255) / 256, 256>>>();
    hist_kernel<<<(NE + 255) / 256, 256>>>(ei);
    scanA<<<dim3(SNB, 2), SCH>>>();
    scanB<<<1, 256>>>();
    scanC<<<dim3(SNB, 2), SCH>>>();
    scatter_kernel<<<(NE + 255) / 256, 256>>>(ei);

    prep_w128<<<256, 256>>>(wq, wk, mw1, mw2);
    prep_wre<<<32, 256>>>(wre);
    prep_wc<<<64, 256>>>(wc);

    node_fused_mma<<<(NN + 127) / 128, 256, NODE_SMEM>>>(h, bq, bk, mb1, mb2, q_p, k_p, P_p, NN);

    edge_logits_v2<<<NE / 128, 256, EDGE2_SMEM>>>(t, ei, bre);
    segment_softmax<<<(NN + 7) / 8, 256>>>();
    edge_out_sorted<<<(NN + 7) / 8, 256>>>(bc, out);
}

// round 7
// speedup vs baseline: 1.6361x; 1.0090x over previous
#include <cuda_runtime.h>
#include <cuda_bf16.h>
#include <math.h>
#include <cstdint>

#define NN 50000
#define NE 400000

// =============== mma.sync helpers ===============
__device__ __forceinline__ uint32_t smem_to_u32(const void* p) {
    uint32_t a;
    asm("{ .reg .u64 t; cvta.to.shared.u64 t, %1; cvt.u32.u64 %0, t; }" : "=r"(a) : "l"(p));
    return a;
}
__device__ __forceinline__ void ldsm_x4(uint32_t addr, uint32_t* r) {
    asm volatile("ldmatrix.sync.aligned.m8n8.x4.shared.b16 {%0,%1,%2,%3}, [%4];"
        : "=r"(r[0]), "=r"(r[1]), "=r"(r[2]), "=r"(r[3]) : "r"(addr));
}
__device__ __forceinline__ void mma_bf16(float* d, const uint32_t* a, const uint32_t* b) {
    asm volatile("mma.sync.aligned.m16n8k16.row.col.f32.bf16.bf16.f32 "
        "{%0,%1,%2,%3}, {%4,%5,%6,%7}, {%8,%9}, {%0,%1,%2,%3};"
        : "+f"(d[0]), "+f"(d[1]), "+f"(d[2]), "+f"(d[3])
        : "r"(a[0]), "r"(a[1]), "r"(a[2]), "r"(a[3]), "r"(b[0]), "r"(b[1]));
}
__device__ __forceinline__ uint32_t a_lane_addr(uint32_t base, int R, int lane, int stride) {
    int t = lane >> 3;
    int row = R + (lane & 7) + (t & 1) * 8;
    int k8  = (t >> 1) * 8;
    return base + row * stride + k8 * 2;
}
__device__ __forceinline__ uint32_t b_lane_addr(uint32_t base, int lane, int stride) {
    int t = lane >> 3;
    int n  = (lane & 7) + (t >> 1) * 8;
    int k8 = (t & 1) * 8;
    return base + n * stride + k8 * 2;
}
template<int KSTEPS>
__device__ __forceinline__ void warp_gemm(
    uint32_t aH, uint32_t aL, uint32_t bH, uint32_t bL, int bstride, float (*acc)[4])
{
#pragma unroll
    for (int ks = 0; ks < KSTEPS; ks++) {
        uint32_t rah[4], ral[4];
        ldsm_x4(aH + ks * 32, rah);
        ldsm_x4(aL + ks * 32, ral);
#pragma unroll
        for (int nbp = 0; nbp < 8; nbp++) {
            uint32_t bh[4], bl[4];
            ldsm_x4(bH + nbp * 16 * bstride + ks * 32, bh);
            ldsm_x4(bL + nbp * 16 * bstride + ks * 32, bl);
            mma_bf16(acc[2 * nbp],     rah, bh);
            mma_bf16(acc[2 * nbp],     rah, bl);
            mma_bf16(acc[2 * nbp],     ral, bh);
            mma_bf16(acc[2 * nbp + 1], rah, bh + 2);
            mma_bf16(acc[2 * nbp + 1], rah, bl + 2);
            mma_bf16(acc[2 * nbp + 1], ral, bh + 2);
        }
    }
}

__device__ __forceinline__ float silu_f(float x) { return x / (1.0f + __expf(-x)); }
__device__ __forceinline__ void split2(float x0, float x1, uint32_t& hi, uint32_t& lo) {
    __nv_bfloat16 h0 = __float2bfloat16(x0), h1 = __float2bfloat16(x1);
    __nv_bfloat16 l0 = __float2bfloat16(x0 - __bfloat162float(h0));
    __nv_bfloat16 l1 = __float2bfloat16(x1 - __bfloat162float(h1));
    __nv_bfloat162 H; H.x = h0; H.y = h1;
    __nv_bfloat162 L; L.x = l0; L.y = l1;
    hi = *(uint32_t*)&H; lo = *(uint32_t*)&L;
}

// =============== scratch globals ===============
__device__ __align__(16) float g_q [NN * 128];
__device__ __align__(16) float g_k [NN * 128];
__device__ __align__(16) float g_P [(size_t)NN * 1024];
__device__ __align__(16) float g_a [(size_t)NE * 8];
__device__ int g_cnt  [NN];
__device__ int g_cntI [NN];
__device__ int g_off  [NN + 1];
__device__ int g_offI [NN + 1];
__device__ int g_order [NE];
__device__ int g_orderI[NE];
#define SCH 512
#define SNB ((NN + SCH - 1) / SCH)
__device__ int g_part[2][SNB];
__device__ int g_pp  [2][SNB];
__device__ __align__(16) __nv_bfloat16 g_wimg [4][2][128 * 136];
__device__ __align__(16) __nv_bfloat16 g_wreimg[2][128 * 72];
__device__ __align__(16) __nv_bfloat16 g_wcimg [8][2][128 * 24];

// =============== weight prep ===============
__global__ void prep_w128(const float* __restrict__ wq, const float* __restrict__ wk,
                          const float* __restrict__ mw1, const float* __restrict__ mw2) {
    int gid = blockIdx.x * blockDim.x + threadIdx.x;
    int m = gid >> 14, idx = gid & 16383;
    const float* W = (m == 0) ? wq : (m == 1) ? wk : (m == 2) ? mw1 : mw2;
    int k = idx >> 7, n = idx & 127;
    float w = W[k * 128 + n];
    __nv_bfloat16 h = __float2bfloat16(w);
    __nv_bfloat16 l = __float2bfloat16(w - __bfloat162float(h));
    g_wimg[m][0][n * 136 + k] = h;
    g_wimg[m][1][n * 136 + k] = l;
}
__global__ void prep_wre(const float* __restrict__ wre) {
    int idx = blockIdx.x * blockDim.x + threadIdx.x;
    int k = idx >> 7, n = idx & 127;
    float w = wre[k * 128 + n];
    __nv_bfloat16 h = __float2bfloat16(w);
    __nv_bfloat16 l = __float2bfloat16(w - __bfloat162float(h));
    g_wreimg[0][n * 72 + k] = h;
    g_wreimg[1][n * 72 + k] = l;
}
__global__ void prep_wc(const float* __restrict__ wc) {
    int gid = blockIdx.x * blockDim.x + threadIdx.x;
    int hh = gid >> 11, idx = gid & 2047;
    int n = idx >> 4, k = idx & 15;
    float w = wc[(hh * 16 + k) * 128 + n];
    __nv_bfloat16 h = __float2bfloat16(w);
    __nv_bfloat16 l = __float2bfloat16(w - __bfloat162float(h));
    g_wcimg[hh][0][n * 24 + k] = h;
    g_wcimg[hh][1][n * 24 + k] = l;
}

// =============== node stage: two roles, 64-row tiles, 2 CTAs/SM ===============
// smem: bias 1024B | A_hi 17408 | A_lo 17408 | W pair 69632  = 105472
#define N2_BIAS 0
#define N2_AH   1024
#define N2_AL   (N2_AH + 17408)
#define N2_W    (N2_AL + 17408)
#define NODE2_SMEM (N2_W + 69632)   // 105472

__device__ __forceinline__ void copy_w_pair(char* smem, const __nv_bfloat16* src, int tid) {
    const uint4* s = (const uint4*)src;
    uint4* d = (uint4*)(smem + N2_W);
#pragma unroll
    for (int i = 0; i < 34; i++) d[tid + 128 * i] = s[tid + 128 * i];   // 69632B
}

__global__ void __launch_bounds__(128, 2) node_all(
    const float* __restrict__ H,
    const float* __restrict__ bq, const float* __restrict__ bk,
    const float* __restrict__ mb1, const float* __restrict__ mb2,
    float* __restrict__ Q, float* __restrict__ K, float* __restrict__ P, int nrows)
{
    extern __shared__ char smem[];
    uint32_t sb = smem_to_u32(smem);
    float* smb = (float*)(smem + N2_BIAS);
    int tid = threadIdx.x, wid = tid >> 5, lane = tid & 31;
    int role = blockIdx.x & 1;
    int tile = blockIdx.x >> 1;
    int row0 = tile * 64;
    int R = wid * 16;
    int g = lane >> 2, tig = lane & 3;

    // biases
    if (role == 0) { smb[tid] = bq[tid]; smb[128 + tid] = bk[tid]; }
    else           { smb[tid] = mb1[tid]; smb[128 + tid] = mb2[tid]; }

    // A = h tile split (64 rows x 32 f4 = 2048 f4)
#pragma unroll
    for (int it = 0; it < 16; it++) {
        int idx = it * 128 + tid;
        int r = idx >> 5, c4 = (idx & 31) * 4;
        float4 x = make_float4(0.f, 0.f, 0.f, 0.f);
        if (row0 + r < nrows) x = *(const float4*)(H + (size_t)(row0 + r) * 128 + c4);
        uint32_t h0, l0, h1, l1;
        split2(x.x, x.y, h0, l0);
        split2(x.z, x.w, h1, l1);
        uint32_t o = (uint32_t)(r * 272 + c4 * 2);
        asm volatile("st.shared.v2.b32 [%0], {%1, %2};" :: "r"(sb + N2_AH + o), "r"(h0), "r"(h1));
        asm volatile("st.shared.v2.b32 [%0], {%1, %2};" :: "r"(sb + N2_AL + o), "r"(l0), "r"(l1));
    }

    uint32_t aH = a_lane_addr(sb + N2_AH, R, lane, 272);
    uint32_t aL = a_lane_addr(sb + N2_AL, R, lane, 272);
    uint64_t bHW = 0, bLW = 0;  // placeholders (unused)
    (void)bHW; (void)bLW;
    uint32_t wH = b_lane_addr(sb + N2_W, lane, 272);
    uint32_t wL = b_lane_addr(sb + N2_W + 34816, lane, 272);

    float acc[16][4];
    int rlo = row0 + R + g, rhi = rlo + 8;
    bool llo = rlo < nrows, lhi = rhi < nrows;

    if (role == 0) {
        // ---------- q, k ----------
        copy_w_pair(smem, &g_wimg[0][0][0], tid);   // wq
        __syncthreads();
#pragma unroll
        for (int i = 0; i < 16; i++) { acc[i][0] = acc[i][1] = acc[i][2] = acc[i][3] = 0.f; }
        warp_gemm<8>(aH, aL, wH, wL, 272, acc);
#pragma unroll
        for (int nb = 0; nb < 16; nb++) {
            int c = nb * 8 + tig * 2;
            if (llo) *(float2*)(Q + (size_t)rlo * 128 + c) = make_float2(acc[nb][0] + smb[c], acc[nb][1] + smb[c + 1]);
            if (lhi) *(float2*)(Q + (size_t)rhi * 128 + c) = make_float2(acc[nb][2] + smb[c], acc[nb][3] + smb[c + 1]);
        }
        __syncthreads();
        copy_w_pair(smem, &g_wimg[1][0][0], tid);   // wk
        __syncthreads();
#pragma unroll
        for (int i = 0; i < 16; i++) { acc[i][0] = acc[i][1] = acc[i][2] = acc[i][3] = 0.f; }
        warp_gemm<8>(aH, aL, wH, wL, 272, acc);
#pragma unroll
        for (int nb = 0; nb < 16; nb++) {
            int c = nb * 8 + tig * 2;
            if (llo) *(float2*)(K + (size_t)rlo * 128 + c) = make_float2(acc[nb][0] + smb[128 + c], acc[nb][1] + smb[128 + c + 1]);
            if (lhi) *(float2*)(K + (size_t)rhi * 128 + c) = make_float2(acc[nb][2] + smb[128 + c], acc[nb][3] + smb[128 + c + 1]);
        }
    } else {
        // ---------- t1 -> v -> P ----------
        copy_w_pair(smem, &g_wimg[2][0][0], tid);   // mw1
        __syncthreads();
#pragma unroll
        for (int i = 0; i < 16; i++) { acc[i][0] = acc[i][1] = acc[i][2] = acc[i][3] = 0.f; }
        warp_gemm<8>(aH, aL, wH, wL, 272, acc);
        __syncthreads();   // done reading A, W
        // write t1 split to A; load mw2
#pragma unroll
        for (int nb = 0; nb < 16; nb++) {
            int c = nb * 8 + tig * 2;
            uint32_t hi, lo;
            split2(silu_f(acc[nb][0] + smb[c]), silu_f(acc[nb][1] + smb[c + 1]), hi, lo);
            uint32_t o = (uint32_t)((R + g) * 272 + c * 2);
            asm volatile("st.shared.b32 [%0], %1;" :: "r"(sb + N2_AH + o), "r"(hi));
            asm volatile("st.shared.b32 [%0], %1;" :: "r"(sb + N2_AL + o), "r"(lo));
            split2(silu_f(acc[nb][2] + smb[c]), silu_f(acc[nb][3] + smb[c + 1]), hi, lo);
            o = (uint32_t)((R + g + 8) * 272 + c * 2);
            asm volatile("st.shared.b32 [%0], %1;" :: "r"(sb + N2_AH + o), "r"(hi));
            asm volatile("st.shared.b32 [%0], %1;" :: "r"(sb + N2_AL + o), "r"(lo));
        }
        copy_w_pair(smem, &g_wimg[3][0][0], tid);   // mw2
        __syncthreads();

#pragma unroll
        for (int i = 0; i < 16; i++) { acc[i][0] = acc[i][1] = acc[i][2] = acc[i][3] = 0.f; }
        warp_gemm<8>(aH, aL, wH, wL, 272, acc);
        __syncthreads();   // done reading A(t1), W
        // write v split to A; load wc heads 0..3 (49152B)
#pragma unroll
        for (int nb = 0; nb < 16; nb++) {
            int c = nb * 8 + tig * 2;
            uint32_t hi, lo;
            split2(acc[nb][0] + smb[128 + c], acc[nb][1] + smb[128 + c + 1], hi, lo);
            uint32_t o = (uint32_t)((R + g) * 272 + c * 2);
            asm volatile("st.shared.b32 [%0], %1;" :: "r"(sb + N2_AH + o), "r"(hi));
            asm volatile("st.shared.b32 [%0], %1;" :: "r"(sb + N2_AL + o), "r"(lo));
            split2(acc[nb][2] + smb[128 + c], acc[nb][3] + smb[128 + c + 1], hi, lo);
            o = (uint32_t)((R + g + 8) * 272 + c * 2);
            asm volatile("st.shared.b32 [%0], %1;" :: "r"(sb + N2_AH + o), "r"(hi));
            asm volatile("st.shared.b32 [%0], %1;" :: "r"(sb + N2_AL + o), "r"(lo));
        }
        {
            const uint4* s = (const uint4*)(&g_wcimg[0][0][0]);
            uint4* d = (uint4*)(smem + N2_W);
#pragma unroll
            for (int i = 0; i < 24; i++) d[tid + 128 * i] = s[tid + 128 * i];  // 49152B
        }
        __syncthreads();

        // P heads 0..3
#pragma unroll
        for (int hh = 0; hh < 4; hh++) {
#pragma unroll
            for (int i = 0; i < 16; i++) { acc[i][0] = acc[i][1] = acc[i][2] = acc[i][3] = 0.f; }
            warp_gemm<1>(aH + hh * 32, aL + hh * 32,
                         b_lane_addr(sb + N2_W + hh * 12288, lane, 48),
                         b_lane_addr(sb + N2_W + hh * 12288 + 6144, lane, 48), 48, acc);
#pragma unroll
            for (int nb = 0; nb < 16; nb++) {
                int c = hh * 128 + nb * 8 + tig * 2;
                if (llo) *(float2*)(P + (size_t)rlo * 1024 + c) = make_float2(acc[nb][0], acc[nb][1]);
                if (lhi) *(float2*)(P + (size_t)rhi * 1024 + c) = make_float2(acc[nb][2], acc[nb][3]);
            }
        }
        __syncthreads();
        {
            const uint4* s = (const uint4*)(&g_wcimg[4][0][0]);
            uint4* d = (uint4*)(smem + N2_W);
#pragma unroll
            for (int i = 0; i < 24; i++) d[tid + 128 * i] = s[tid + 128 * i];
        }
        __syncthreads();

        // P heads 4..7
#pragma unroll
        for (int hh = 4; hh < 8; hh++) {
#pragma unroll
            for (int i = 0; i < 16; i++) { acc[i][0] = acc[i][1] = acc[i][2] = acc[i][3] = 0.f; }
            warp_gemm<1>(aH + hh * 32, aL + hh * 32,
                         b_lane_addr(sb + N2_W + (hh - 4) * 12288, lane, 48),
                         b_lane_addr(sb + N2_W + (hh - 4) * 12288 + 6144, lane, 48), 48, acc);
#pragma unroll
            for (int nb = 0; nb < 16; nb++) {
                int c = hh * 128 + nb * 8 + tig * 2;
                if (llo) *(float2*)(P + (size_t)rlo * 1024 + c) = make_float2(acc[nb][0], acc[nb][1]);
                if (lhi) *(float2*)(P + (size_t)rhi * 1024 + c) = make_float2(acc[nb][2], acc[nb][3]);
            }
        }
    }
}

// =============== edge logits v2 (unchanged) ===============
#define EB_BIAS 0
#define EB_TH   512
#define EB_TL   (EB_TH + 18432)
#define EB_WH   (EB_TL + 18432)
#define EB_WL   (EB_WH + 18432)
#define EB_RE   512
#define EDGE2_SMEM (EB_WL + 18432)

__global__ void __launch_bounds__(256) edge_logits_v2(
    const float* __restrict__ T, const int* __restrict__ EI, const float* __restrict__ BRE)
{
    extern __shared__ char smem[];
    uint32_t sb = smem_to_u32(smem);
    float* smb = (float*)(smem + EB_BIAS);
    float* sRe = (float*)(smem + EB_RE);
    int tid = threadIdx.x, wid = tid >> 5, lane = tid & 31;
    int e0 = blockIdx.x * 128;
    int R = wid * 16;
    int g = lane >> 2, tig = lane & 3;

    if (tid < 128) smb[tid] = BRE[tid];
    {
        const uint4* s = (const uint4*)(&g_wreimg[0][0]);
        uint4* d = (uint4*)(smem + EB_WH);
#pragma unroll
        for (int i = 0; i < 9; i++) d[tid + 256 * i] = s[tid + 256 * i];
    }
#pragma unroll
    for (int it = 0; it < 8; it++) {
        int idx = it * 256 + tid;
        int r = idx >> 4, c4 = (idx & 15) * 4;
        float4 x = *(const float4*)(T + (size_t)(e0 + r) * 64 + c4);
        uint32_t h0, l0, h1, l1;
        split2(x.x, x.y, h0, l0);
        split2(x.z, x.w, h1, l1);
        uint32_t o = (uint32_t)(r * 144 + c4 * 2);
        asm volatile("st.shared.v2.b32 [%0], {%1, %2};" :: "r"(sb + EB_TH + o), "r"(h0), "r"(h1));
        asm volatile("st.shared.v2.b32 [%0], {%1, %2};" :: "r"(sb + EB_TL + o), "r"(l0), "r"(l1));
    }
    __syncthreads();

    float acc[16][4];
#pragma unroll
    for (int i = 0; i < 16; i++) { acc[i][0] = acc[i][1] = acc[i][2] = acc[i][3] = 0.f; }
    warp_gemm<4>(a_lane_addr(sb + EB_TH, R, lane, 144), a_lane_addr(sb + EB_TL, R, lane, 144),
                 b_lane_addr(sb + EB_WH, lane, 144),    b_lane_addr(sb + EB_WL, lane, 144), 144, acc);
    __syncthreads();

#pragma unroll
    for (int nb = 0; nb < 16; nb++) {
        int c = nb * 8 + tig * 2;
        float b0 = smb[c], b1 = smb[c + 1];
        *(float2*)(sRe + (R + g) * 132 + c)     = make_float2(silu_f(acc[nb][0] + b0), silu_f(acc[nb][1] + b1));
        *(float2*)(sRe + (R + g + 8) * 132 + c) = make_float2(silu_f(acc[nb][2] + b0), silu_f(acc[nb][3] + b1));
    }
    __syncthreads();

#pragma unroll
    for (int i = 0; i < 16; i++) {
        int el = wid * 16 + i;
        int e = e0 + el;
        int nj = EI[e];
        int ni = EI[NE + e];
        float4 q4 = *(const float4*)(g_q + (size_t)ni * 128 + lane * 4);
        float4 k4 = *(const float4*)(g_k + (size_t)nj * 128 + lane * 4);
        float4 r4 = *(const float4*)(sRe + el * 132 + lane * 4);
        float p = q4.x * k4.x * r4.x + q4.y * k4.y * r4.y
                + q4.z * k4.z * r4.z + q4.w * k4.w * r4.w;
        p += __shfl_xor_sync(0xffffffffu, p, 1);
        p += __shfl_xor_sync(0xffffffffu, p, 2);
        if ((lane & 3) == 0) g_a[(size_t)e * 8 + (lane >> 2)] = p;
    }
}

// =============== CSR machinery (unchanged) ===============
__global__ void init_kernel() {
    int i = blockIdx.x * blockDim.x + threadIdx.x;
    if (i < NN) { g_cnt[i] = 0; g_cntI[i] = 0; }
}
__global__ void hist_kernel(const int* __restrict__ EI) {
    int e = blockIdx.x * blockDim.x + threadIdx.x;
    if (e < NE) {
        atomicAdd(&g_cnt[EI[e]], 1);
        atomicAdd(&g_cntI[EI[NE + e]], 1);
    }
}
__global__ void __launch_bounds__(SCH) scanA() {
    const int* cnt = blockIdx.y ? g_cntI : g_cnt;
    __shared__ int sm[SCH];
    int tid = threadIdx.x;
    int i = blockIdx.x * SCH + tid;
    sm[tid] = (i < NN) ? cnt[i] : 0;
    __syncthreads();
#pragma unroll
    for (int off = SCH / 2; off > 0; off >>= 1) {
        if (tid < off) sm[tid] += sm[tid + off];
        __syncthreads();
    }
    if (tid == 0) g_part[blockIdx.y][blockIdx.x] = sm[0];
}
__global__ void __launch_bounds__(256) scanB() {
    __shared__ int sm[2][128];
    int tid = threadIdx.x;
    int y = tid >> 7, x = tid & 127;
    sm[y][x] = (x < SNB) ? g_part[y][x] : 0;
    __syncthreads();
#pragma unroll
    for (int off = 1; off < 128; off <<= 1) {
        int v = (x >= off) ? sm[y][x - off] : 0;
        __syncthreads();
        sm[y][x] += v;
        __syncthreads();
    }
    if (x < SNB) g_pp[y][x] = sm[y][x] - g_part[y][x];
    if (x == SNB - 1) {
        if (y == 0) g_off[NN]  = sm[0][x];
        else        g_offI[NN] = sm[1][x];
    }
}
__global__ void __launch_bounds__(SCH) scanC() {
    int* cnt = blockIdx.y ? g_cntI : g_cnt;
    int* off = blockIdx.y ? g_offI : g_off;
    __shared__ int sm[SCH];
    int tid = threadIdx.x;
    int i = blockIdx.x * SCH + tid;
    int self = (i < NN) ? cnt[i] : 0;
    sm[tid] = self;
    __syncthreads();
#pragma unroll
    for (int o = 1; o < SCH; o <<= 1) {
        int v = (tid >= o) ? sm[tid - o] : 0;
        __syncthreads();
        sm[tid] += v;
        __syncthreads();
    }
    if (i < NN) {
        int pref = g_pp[blockIdx.y][blockIdx.x] + sm[tid] - self;
        off[i] = pref;
        cnt[i] = pref;
    }
}
__global__ void scatter_kernel(const int* __restrict__ EI) {
    int e = blockIdx.x * blockDim.x + threadIdx.x;
    if (e < NE) {
        int pj = atomicAdd(&g_cnt[EI[e]], 1);
        g_order[pj] = e;
        int pi = atomicAdd(&g_cntI[EI[NE + e]], 1);
        g_orderI[pi] = e;
    }
}

// =============== segment softmax (unchanged) ===============
__global__ void __launch_bounds__(256) segment_softmax() {
    int i = blockIdx.x * 8 + (threadIdx.x >> 5);
    int lane = threadIdx.x & 31;
    if (i >= NN) return;
    int s = g_offI[i];
    int d = g_offI[i + 1] - s;
    if (d == 0) return;
    int nv = d * 8;
    int iters = (nv + 31) >> 5;
    const int CAP = 8;
    float vals[CAP];

    float mx = -1e30f;
#pragma unroll
    for (int it = 0; it < CAP; it++) {
        if (it < iters) {
            int v = it * 32 + lane;
            float val = -1e30f;
            if (v < nv) val = g_a[(size_t)g_orderI[s + (v >> 3)] * 8 + (v & 7)];
            vals[it] = val;
            mx = fmaxf(mx, val);
        }
    }
    for (int it = CAP; it < iters; it++) {
        int v = it * 32 + lane;
        if (v < nv) mx = fmaxf(mx, g_a[(size_t)g_orderI[s + (v >> 3)] * 8 + (v & 7)]);
    }
    mx = fmaxf(mx, __shfl_xor_sync(0xffffffffu, mx, 16));
    mx = fmaxf(mx, __shfl_xor_sync(0xffffffffu, mx, 8));

    float sum = 0.f;
#pragma unroll
    for (int it = 0; it < CAP; it++) {
        if (it < iters) {
            int v = it * 32 + lane;
            float ex = 0.f;
            if (v < nv) ex = __expf(vals[it] - mx);
            vals[it] = ex;
            sum += ex;
        }
    }
    for (int it = CAP; it < iters; it++) {
        int v = it * 32 + lane;
        if (v < nv) sum += __expf(g_a[(size_t)g_orderI[s + (v >> 3)] * 8 + (v & 7)] - mx);
    }
    sum += __shfl_xor_sync(0xffffffffu, sum, 16);
    sum += __shfl_xor_sync(0xffffffffu, sum, 8);

    float scale = sqrtf((float)d) * 0.25f / sum;
#pragma unroll
    for (int it = 0; it < CAP; it++) {
        if (it < iters) {
            int v = it * 32 + lane;
            if (v < nv) g_a[(size_t)g_orderI[s + (v >> 3)] * 8 + (v & 7)] = vals[it] * scale;
        }
    }
    for (int it = CAP; it < iters; it++) {
        int v = it * 32 + lane;
        if (v < nv) {
            size_t idx = (size_t)g_orderI[s + (v >> 3)] * 8 + (v & 7);
            g_a[idx] = __expf(g_a[idx] - mx) * scale;
        }
    }
}

// =============== output (unchanged) ===============
__global__ void __launch_bounds__(256) edge_out_sorted(
    const float* __restrict__ BC, float* __restrict__ OUT)
{
    int j = blockIdx.x * 8 + (threadIdx.x >> 5);
    int lane = threadIdx.x & 31;
    if (j >= NN) return;
    int s = g_off[j], e_end = g_off[j + 1];
    if (s == e_end) return;

    const float* Pj = g_P + (size_t)j * 1024;
    float4 p[8];
#pragma unroll
    for (int h = 0; h < 8; h++)
        p[h] = *(const float4*)(Pj + h * 128 + lane * 4);
    float4 b4 = *(const float4*)(BC + lane * 4);

    for (int x = s; x < e_end; x++) {
        int e = g_order[x];
        float w = 0.f;
        if (lane < 8) w = g_a[(size_t)e * 8 + lane];

        float4 acc = b4;
#pragma unroll
        for (int h = 0; h < 8; h++) {
            float wh = __shfl_sync(0xffffffffu, w, h);
            acc.x = fmaf(wh, p[h].x, acc.x);
            acc.y = fmaf(wh, p[h].y, acc.y);
            acc.z = fmaf(wh, p[h].z, acc.z);
            acc.w = fmaf(wh, p[h].w, acc.w);
        }
        *(float4*)(OUT + (size_t)e * 128 + lane * 4) = acc;
    }
}

// =============== launch ===============
extern "C" void kernel_launch(void* const* d_in, const int* in_sizes, int n_in,
                              void* d_out, int out_size)
{
    const float* h   = (const float*)d_in[0];
    const float* t   = (const float*)d_in[1];
    const int*   ei  = (const int*)  d_in[2];
    const float* wq  = (const float*)d_in[3];
    const float* bq  = (const float*)d_in[4];
    const float* wk  = (const float*)d_in[5];
    const float* bk  = (const float*)d_in[6];
    const float* wre = (const float*)d_in[7];
    const float* bre = (const float*)d_in[8];
    const float* mw1 = (const float*)d_in[9];
    const float* mb1 = (const float*)d_in[10];
    const float* mw2 = (const float*)d_in[11];
    const float* mb2 = (const float*)d_in[12];
    const float* wc  = (const float*)d_in[13];
    const float* bc  = (const float*)d_in[14];
    float* out = (float*)d_out;

    (void)in_sizes; (void)n_in; (void)out_size;

    cudaFuncSetAttribute(node_all,       cudaFuncAttributeMaxDynamicSharedMemorySize, NODE2_SMEM);
    cudaFuncSetAttribute(edge_logits_v2, cudaFuncAttributeMaxDynamicSharedMemorySize, EDGE2_SMEM);

    float *q_p, *k_p, *P_p;
    cudaGetSymbolAddress((void**)&q_p, g_q);
    cudaGetSymbolAddress((void**)&k_p, g_k);
    cudaGetSymbolAddress((void**)&P_p, g_P);

    init_kernel<<<(NN + 255) / 256, 256>>>();
    hist_kernel<<<(NE + 255) / 256, 256>>>(ei);
    scanA<<<dim3(SNB, 2), SCH>>>();
    scanB<<<1, 256>>>();
    scanC<<<dim3(SNB, 2), SCH>>>();
    scatter_kernel<<<(NE + 255) / 256, 256>>>(ei);

    prep_w128<<<256, 256>>>(wq, wk, mw1, mw2);
    prep_wre<<<32, 256>>>(wre);
    prep_wc<<<64, 256>>>(wc);

    int ntiles = (NN + 63) / 64;   // 782
    node_all<<<ntiles * 2, 128, NODE2_SMEM>>>(h, bq, bk, mb1, mb2, q_p, k_p, P_p, NN);

    edge_logits_v2<<<NE / 128, 256, EDGE2_SMEM>>>(t, ei, bre);
    segment_softmax<<<(NN + 7) / 8, 256>>>();
    edge_out_sorted<<<(NN + 7) / 8, 256>>>(bc, out);
}